// round 9
// baseline (speedup 1.0000x reference)
#include <cuda_runtime.h>
#include <math.h>
#include <stdint.h>

#define S_LEN 2048
#define T_LEN 2048
#define BATCH 2
#define EDIM  1024
#define HEADS 16
#define HDIM  64
#define HD    (HEADS*HDIM)   /* 1024 */

// ---------------- scratch (static device globals; no allocation) ----------
// pre-split bf16x2 operands: *H = hi words, *L = residual words.
__device__ uint32_t g_encH[4096*512], g_encL[4096*512];   // enc  (T*B, E/2)
__device__ uint32_t g_inH [4096*512], g_inL [4096*512];   // inp  (S*B, E/2)
__device__ uint32_t g_WkvH[512*2048], g_WkvL[512*2048];   // Wkv  (E/2, 2HD)
__device__ uint32_t g_WqH [512*1024], g_WqL [512*1024];   // Wq   (E/2, HD)
__device__ uint32_t g_WpH [512*1024], g_WpL [512*1024];   // Wp   (HD/2, E)
__device__ uint32_t g_Kh[BATCH*HEADS*T_LEN*32], g_Kl[BATCH*HEADS*T_LEN*32]; // (B,H,T,D/2)
__device__ uint32_t g_Qh[BATCH*HEADS*S_LEN*32], g_Ql[BATCH*HEADS*S_LEN*32]; // (B,H,S,D/2)
__device__ float    g_V [BATCH*HEADS*T_LEN*HDIM];                            // (B,H,T,D)
__device__ uint32_t g_AVh[4096*512], g_AVl[4096*512];     // (S*B, HD/2)

// ---------------- bf16 split helpers ---------------------------------------
__device__ __forceinline__ uint32_t bfbits(float x) {   // rn-even bf16, as fp32 bits
    uint32_t u = __float_as_uint(x);
    return (u + 0x7FFFu + ((u >> 16) & 1u)) & 0xFFFF0000u;
}
// split-and-pack (even, odd) pair -> bf16x2 hi word + bf16x2 residual word
__device__ __forceinline__ void sp2(float e, float o, uint32_t& hw, uint32_t& lw) {
    uint32_t he = bfbits(e), ho = bfbits(o);
    float re = e - __uint_as_float(he);
    float ro = o - __uint_as_float(ho);
    hw = __byte_perm(he, ho, 0x7632);
    lw = __byte_perm(bfbits(re), bfbits(ro), 0x7632);
}
__device__ __forceinline__ void mma_bf16(float* c, uint32_t a0, uint32_t a1,
                                         uint32_t a2, uint32_t a3,
                                         uint32_t b0, uint32_t b1) {
    asm volatile(
        "mma.sync.aligned.m16n8k16.row.col.f32.bf16.bf16.f32 "
        "{%0,%1,%2,%3}, {%4,%5,%6,%7}, {%8,%9}, {%0,%1,%2,%3};"
        : "+f"(c[0]), "+f"(c[1]), "+f"(c[2]), "+f"(c[3])
        : "r"(a0), "r"(a1), "r"(a2), "r"(a3), "r"(b0), "r"(b1));
}

// ===========================================================================
// conversion kernels (run once per launch; memory-bound)
// ===========================================================================
// W (1024, N) fp32 -> (512, N) u32 pairs along k (rows 2k, 2k+1)
__global__ __launch_bounds__(256) void conv_b(const float* __restrict__ W,
                                              uint32_t* __restrict__ Wh,
                                              uint32_t* __restrict__ Wl, int N) {
    int idx = blockIdx.x * 256 + threadIdx.x;
    int k2 = idx / (N / 4), n4 = (idx % (N / 4)) * 4;
    const float* r0 = W + (size_t)(2 * k2) * N + n4;
    float4 a = *(const float4*)r0;
    float4 b = *(const float4*)(r0 + N);
    uint4 h, l;
    sp2(a.x, b.x, h.x, l.x); sp2(a.y, b.y, h.y, l.y);
    sp2(a.z, b.z, h.z, l.z); sp2(a.w, b.w, h.w, l.w);
    *(uint4*)(Wh + (size_t)k2 * N + n4) = h;
    *(uint4*)(Wl + (size_t)k2 * N + n4) = l;
}
// A (4096, 1024) fp32 -> (4096, 512) u32 pairs along k (contiguous cols)
__global__ __launch_bounds__(256) void conv_a(const float* __restrict__ A,
                                              uint32_t* __restrict__ Ah,
                                              uint32_t* __restrict__ Al) {
    int idx = blockIdx.x * 256 + threadIdx.x;
    int m = idx >> 7, c8 = (idx & 127) * 8;
    float4 f0 = *(const float4*)(A + (size_t)m * 1024 + c8);
    float4 f1 = *(const float4*)(A + (size_t)m * 1024 + c8 + 4);
    uint4 h, l;
    sp2(f0.x, f0.y, h.x, l.x); sp2(f0.z, f0.w, h.y, l.y);
    sp2(f1.x, f1.y, h.z, l.z); sp2(f1.z, f1.w, h.w, l.w);
    *(uint4*)(Ah + (size_t)m * 512 + c8 / 2) = h;
    *(uint4*)(Al + (size_t)m * 512 + c8 / 2) = l;
}

// ===========================================================================
// 3x-bf16 GEMM on pre-split operands. D(128x128)=A(Mx1024)@B(1024xN)+bias.
// 8 warps (2m x 4n), m16n8k16, K-chunk 16 (8 kpairs). Loaders are pure copies.
// MODE 0: kv -> g_Kh/g_Kl (split) + g_V (fp32). MODE 1: q (+u) -> g_Qh/g_Ql.
// MODE 2: -> out fp32.
// ===========================================================================
#define PADM 136

template<int MODE>
__global__ __launch_bounds__(256) void mma_gemm(
    const uint32_t* __restrict__ Ahg, const uint32_t* __restrict__ Alg,
    const uint32_t* __restrict__ Bhg, const uint32_t* __restrict__ Blg,
    const float* __restrict__ bias, const float* __restrict__ u,
    float* __restrict__ out, int N)
{
    __shared__ uint32_t Ah[2][8][PADM], Al[2][8][PADM];
    __shared__ uint32_t Bh[2][8][PADM], Bl[2][8][PADM];

    const int tid  = threadIdx.x;
    const int wid  = tid >> 5, lane = tid & 31;
    const int g    = lane >> 2, tg = lane & 3;
    const int wm   = wid >> 2,  wn = wid & 3;
    const int m0   = blockIdx.y * 128, n0 = blockIdx.x * 128;

    const int aRow = tid >> 2;          // 0..63
    const int aKp  = (tid & 3) * 2;     // kpair base 0,2,4,6
    const int bKp  = tid >> 5;          // kpair 0..7
    const int bCol = (tid & 31) * 4;    // 0..124

    float acc[4][4][4] = {};

    uint2 ah0, ah1, al0, al1;
    uint4 bh4, bl4;
    #define GLOAD(k2) do { \
        ah0 = *(const uint2*)(Ahg + (size_t)(m0 + aRow)      * 512 + (k2) + aKp); \
        ah1 = *(const uint2*)(Ahg + (size_t)(m0 + aRow + 64) * 512 + (k2) + aKp); \
        al0 = *(const uint2*)(Alg + (size_t)(m0 + aRow)      * 512 + (k2) + aKp); \
        al1 = *(const uint2*)(Alg + (size_t)(m0 + aRow + 64) * 512 + (k2) + aKp); \
        bh4 = *(const uint4*)(Bhg + (size_t)((k2) + bKp) * N + n0 + bCol); \
        bl4 = *(const uint4*)(Blg + (size_t)((k2) + bKp) * N + n0 + bCol); \
    } while (0)
    #define SSTORE(buf) do { \
        Ah[buf][aKp][aRow]          = ah0.x; Ah[buf][aKp + 1][aRow]          = ah0.y; \
        Ah[buf][aKp][aRow + 64]     = ah1.x; Ah[buf][aKp + 1][aRow + 64]     = ah1.y; \
        Al[buf][aKp][aRow]          = al0.x; Al[buf][aKp + 1][aRow]          = al0.y; \
        Al[buf][aKp][aRow + 64]     = al1.x; Al[buf][aKp + 1][aRow + 64]     = al1.y; \
        *(uint4*)&Bh[buf][bKp][bCol] = bh4; \
        *(uint4*)&Bl[buf][bKp][bCol] = bl4; \
    } while (0)

    GLOAD(0);
    SSTORE(0);
    __syncthreads();

    const int NKB = 64;
    for (int kb = 0; kb < NKB; kb++) {
        int buf = kb & 1;
        if (kb + 1 < NKB) GLOAD((kb + 1) * 8);

        uint32_t ah[4][4], al4[4][4];
        #pragma unroll
        for (int mt = 0; mt < 4; mt++) {
            int r = wm * 64 + mt * 16 + g;
            ah[mt][0]  = Ah[buf][tg][r];
            ah[mt][1]  = Ah[buf][tg][r + 8];
            ah[mt][2]  = Ah[buf][tg + 4][r];
            ah[mt][3]  = Ah[buf][tg + 4][r + 8];
            al4[mt][0] = Al[buf][tg][r];
            al4[mt][1] = Al[buf][tg][r + 8];
            al4[mt][2] = Al[buf][tg + 4][r];
            al4[mt][3] = Al[buf][tg + 4][r + 8];
        }
        uint32_t bh[4][2], bl4r[4][2];
        #pragma unroll
        for (int nt = 0; nt < 4; nt++) {
            int c = wn * 32 + nt * 8 + g;
            bh[nt][0]   = Bh[buf][tg][c];
            bh[nt][1]   = Bh[buf][tg + 4][c];
            bl4r[nt][0] = Bl[buf][tg][c];
            bl4r[nt][1] = Bl[buf][tg + 4][c];
        }
        #pragma unroll
        for (int mt = 0; mt < 4; mt++)
            #pragma unroll
            for (int nt = 0; nt < 4; nt++) {
                float* c = acc[mt][nt];
                mma_bf16(c, ah[mt][0], ah[mt][1], ah[mt][2], ah[mt][3],
                            bh[nt][0], bh[nt][1]);
                mma_bf16(c, ah[mt][0], ah[mt][1], ah[mt][2], ah[mt][3],
                            bl4r[nt][0], bl4r[nt][1]);
                mma_bf16(c, al4[mt][0], al4[mt][1], al4[mt][2], al4[mt][3],
                            bh[nt][0], bh[nt][1]);
            }

        if (kb + 1 < NKB) SSTORE(1 - buf);
        __syncthreads();
    }
    #undef GLOAD
    #undef SSTORE

    // ---------------- epilogue ------------------------------------------
    #pragma unroll
    for (int mt = 0; mt < 4; mt++) {
        #pragma unroll
        for (int nt = 0; nt < 4; nt++) {
            int n  = n0 + wn * 32 + nt * 8 + tg * 2;
            int mA = m0 + wm * 64 + mt * 16 + g;
            float bs0 = __ldg(bias + n), bs1 = __ldg(bias + n + 1);
            float v00 = acc[mt][nt][0] + bs0;
            float v01 = acc[mt][nt][1] + bs1;
            float v10 = acc[mt][nt][2] + bs0;
            float v11 = acc[mt][nt][3] + bs1;
            int t0 = mA >> 1, bb = mA & 1;
            int t1 = (mA + 8) >> 1;
            if (MODE == 0) {
                if (n < HD) {
                    int h = n >> 6, d2 = (n & 63) >> 1;
                    size_t base = ((size_t)(bb * HEADS + h)) * T_LEN;
                    uint32_t hw, lw;
                    sp2(v00, v01, hw, lw);
                    g_Kh[(base + t0) * 32 + d2] = hw;
                    g_Kl[(base + t0) * 32 + d2] = lw;
                    sp2(v10, v11, hw, lw);
                    g_Kh[(base + t1) * 32 + d2] = hw;
                    g_Kl[(base + t1) * 32 + d2] = lw;
                } else {
                    int nn = n - HD;
                    int h = nn >> 6, d = nn & 63;
                    size_t base = (((size_t)(bb * HEADS + h)) * T_LEN) * HDIM + d;
                    g_V[base + (size_t)t0 * HDIM]     = v00;
                    g_V[base + (size_t)t0 * HDIM + 1] = v01;
                    g_V[base + (size_t)t1 * HDIM]     = v10;
                    g_V[base + (size_t)t1 * HDIM + 1] = v11;
                }
            } else if (MODE == 1) {
                float u0 = __ldg(u + n), u1 = __ldg(u + n + 1);
                int h = n >> 6, d2 = (n & 63) >> 1;
                size_t base = ((size_t)(bb * HEADS + h)) * S_LEN;
                uint32_t hw, lw;
                sp2(v00 + u0, v01 + u1, hw, lw);
                g_Qh[(base + t0) * 32 + d2] = hw;
                g_Ql[(base + t0) * 32 + d2] = lw;
                sp2(v10 + u0, v11 + u1, hw, lw);
                g_Qh[(base + t1) * 32 + d2] = hw;
                g_Ql[(base + t1) * 32 + d2] = lw;
            } else {
                out[(size_t)mA * EDIM + n]           = v00;
                out[(size_t)mA * EDIM + n + 1]       = v01;
                out[(size_t)(mA + 8) * EDIM + n]     = v10;
                out[(size_t)(mA + 8) * EDIM + n + 1] = v11;
            }
        }
    }
}

// ===========================================================================
// Flash attention, 3x-bf16 m16n8k16, pre-split K/Q inputs, split AV output.
// ===========================================================================
#define PADT 68
#define PADP 36

__global__ __launch_bounds__(256) void attn_bf16(const unsigned char* __restrict__ mask)
{
    extern __shared__ uint32_t smu[];
    uint32_t* Kh = smu;
    uint32_t* Kl = Kh + 32 * PADT;
    uint32_t* Vh = Kl + 32 * PADT;
    uint32_t* Vl = Vh + 32 * PADT;
    uint32_t* Ph = Vl + 32 * PADT;
    uint32_t* Pl = Ph + 128 * PADP;

    const int bh = blockIdx.y;
    const int b  = bh >> 4;
    const int h  = bh & 15;
    const int s0 = blockIdx.x * 128;
    const int tid = threadIdx.x;
    const int wid = tid >> 5, lane = tid & 31;
    const int g   = lane >> 2, tg = lane & 3;
    const int rowA = wid * 16 + g;

    const uint32_t* Khg = g_Kh + (size_t)bh * T_LEN * 32;
    const uint32_t* Klg = g_Kl + (size_t)bh * T_LEN * 32;
    const float*    Vg  = g_V  + (size_t)bh * T_LEN * HDIM;

    // ---- Q fragments: direct pre-split loads ----
    uint32_t qh[4][4], ql[4][4];
    {
        const uint32_t* qh0 = g_Qh + ((size_t)bh * S_LEN + s0 + rowA) * 32;
        const uint32_t* qh1 = qh0 + 8 * 32;
        const uint32_t* ql0 = g_Ql + ((size_t)bh * S_LEN + s0 + rowA) * 32;
        const uint32_t* ql1 = ql0 + 8 * 32;
        #pragma unroll
        for (int ks = 0; ks < 4; ks++) {
            qh[ks][0] = qh0[ks * 8 + tg];
            qh[ks][1] = qh1[ks * 8 + tg];
            qh[ks][2] = qh0[ks * 8 + tg + 4];
            qh[ks][3] = qh1[ks * 8 + tg + 4];
            ql[ks][0] = ql0[ks * 8 + tg];
            ql[ks][1] = ql1[ks * 8 + tg];
            ql[ks][2] = ql0[ks * 8 + tg + 4];
            ql[ks][3] = ql1[ks * 8 + tg + 4];
        }
    }

    float o[8][4] = {};
    float m0 = -1e30f, m1 = -1e30f, l0 = 0.f, l1 = 0.f;

    for (int j0 = 0; j0 < T_LEN; j0 += 64) {
        __syncthreads();

        // ---- K loader: pure u32 copy + transpose ----
        {
            int r = tid >> 2;              // 0..63
            int q8 = (tid & 3) * 8;        // d2 base
            uint4 k0 = *(const uint4*)(Khg + (size_t)(j0 + r) * 32 + q8);
            uint4 k1 = *(const uint4*)(Khg + (size_t)(j0 + r) * 32 + q8 + 4);
            Kh[(q8 + 0) * PADT + r] = k0.x; Kh[(q8 + 1) * PADT + r] = k0.y;
            Kh[(q8 + 2) * PADT + r] = k0.z; Kh[(q8 + 3) * PADT + r] = k0.w;
            Kh[(q8 + 4) * PADT + r] = k1.x; Kh[(q8 + 5) * PADT + r] = k1.y;
            Kh[(q8 + 6) * PADT + r] = k1.z; Kh[(q8 + 7) * PADT + r] = k1.w;
            uint4 l0w = *(const uint4*)(Klg + (size_t)(j0 + r) * 32 + q8);
            uint4 l1w = *(const uint4*)(Klg + (size_t)(j0 + r) * 32 + q8 + 4);
            Kl[(q8 + 0) * PADT + r] = l0w.x; Kl[(q8 + 1) * PADT + r] = l0w.y;
            Kl[(q8 + 2) * PADT + r] = l0w.z; Kl[(q8 + 3) * PADT + r] = l0w.w;
            Kl[(q8 + 4) * PADT + r] = l1w.x; Kl[(q8 + 5) * PADT + r] = l1w.y;
            Kl[(q8 + 6) * PADT + r] = l1w.z; Kl[(q8 + 7) * PADT + r] = l1w.w;
        }
        // ---- V loader: fp32 + split (pairs along t) ----
        #pragma unroll
        for (int it = 0; it < 2; it++) {
            int idx = tid + it * 256;
            int r2 = idx >> 4, c = (idx & 15) * 4;
            float4 va = *(const float4*)(Vg + (size_t)(j0 + 2 * r2)     * HDIM + c);
            float4 vb = *(const float4*)(Vg + (size_t)(j0 + 2 * r2 + 1) * HDIM + c);
            uint4 wh, wl;
            sp2(va.x, vb.x, wh.x, wl.x);
            sp2(va.y, vb.y, wh.y, wl.y);
            sp2(va.z, vb.z, wh.z, wl.z);
            sp2(va.w, vb.w, wh.w, wl.w);
            *(uint4*)&Vh[r2 * PADT + c] = wh;
            *(uint4*)&Vl[r2 * PADT + c] = wl;
        }
        // ---- mask OR-scan ----
        uint32_t mor = 0;
        #pragma unroll
        for (int it = 0; it < 2; it++) {
            int idx = tid + it * 256;
            int r = idx >> 2, c16 = (idx & 3) * 16;
            uint4 mv = *(const uint4*)(mask + (size_t)(s0 + r) * T_LEN + j0 + c16);
            mor |= mv.x | mv.y | mv.z | mv.w;
        }
        int any_mask = __syncthreads_or((int)mor);

        // ---- S = Q K^T ----
        float sc[8][4] = {};
        #pragma unroll
        for (int ks = 0; ks < 4; ks++) {
            #pragma unroll
            for (int nt = 0; nt < 8; nt++) {
                int n = nt * 8 + g;
                uint32_t b0h = Kh[(ks * 8 + tg)     * PADT + n];
                uint32_t b1h = Kh[(ks * 8 + tg + 4) * PADT + n];
                uint32_t b0l = Kl[(ks * 8 + tg)     * PADT + n];
                uint32_t b1l = Kl[(ks * 8 + tg + 4) * PADT + n];
                mma_bf16(sc[nt], qh[ks][0], qh[ks][1], qh[ks][2], qh[ks][3], b0h, b1h);
                mma_bf16(sc[nt], qh[ks][0], qh[ks][1], qh[ks][2], qh[ks][3], b0l, b1l);
                mma_bf16(sc[nt], ql[ks][0], ql[ks][1], ql[ks][2], ql[ks][3], b0h, b1h);
            }
        }

        #pragma unroll
        for (int nt = 0; nt < 8; nt++) {
            sc[nt][0] *= 0.125f; sc[nt][1] *= 0.125f;
            sc[nt][2] *= 0.125f; sc[nt][3] *= 0.125f;
        }
        if (any_mask) {
            int sg0 = s0 + rowA, sg1 = sg0 + 8;
            #pragma unroll
            for (int nt = 0; nt < 8; nt++) {
                int cg = j0 + nt * 8 + tg * 2;
                const unsigned char* m0p = mask + (size_t)sg0 * T_LEN + cg;
                const unsigned char* m1p = mask + (size_t)sg1 * T_LEN + cg;
                if (m0p[0]) sc[nt][0] = -INFINITY;
                if (m0p[1]) sc[nt][1] = -INFINITY;
                if (m1p[0]) sc[nt][2] = -INFINITY;
                if (m1p[1]) sc[nt][3] = -INFINITY;
            }
        }

        // ---- warp-local online softmax ----
        float mx0 = -1e30f, mx1 = -1e30f;
        #pragma unroll
        for (int nt = 0; nt < 8; nt++) {
            mx0 = fmaxf(mx0, fmaxf(sc[nt][0], sc[nt][1]));
            mx1 = fmaxf(mx1, fmaxf(sc[nt][2], sc[nt][3]));
        }
        mx0 = fmaxf(mx0, __shfl_xor_sync(0xffffffffu, mx0, 1));
        mx0 = fmaxf(mx0, __shfl_xor_sync(0xffffffffu, mx0, 2));
        mx1 = fmaxf(mx1, __shfl_xor_sync(0xffffffffu, mx1, 1));
        mx1 = fmaxf(mx1, __shfl_xor_sync(0xffffffffu, mx1, 2));

        float mn0 = fmaxf(m0, mx0), mn1 = fmaxf(m1, mx1);
        float cr0 = __expf(m0 - mn0), cr1 = __expf(m1 - mn1);
        float ps0 = 0.f, ps1 = 0.f;
        #pragma unroll
        for (int nt = 0; nt < 8; nt++) {
            sc[nt][0] = __expf(sc[nt][0] - mn0);
            sc[nt][1] = __expf(sc[nt][1] - mn0);
            sc[nt][2] = __expf(sc[nt][2] - mn1);
            sc[nt][3] = __expf(sc[nt][3] - mn1);
            ps0 += sc[nt][0] + sc[nt][1];
            ps1 += sc[nt][2] + sc[nt][3];
        }
        ps0 += __shfl_xor_sync(0xffffffffu, ps0, 1);
        ps0 += __shfl_xor_sync(0xffffffffu, ps0, 2);
        ps1 += __shfl_xor_sync(0xffffffffu, ps1, 1);
        ps1 += __shfl_xor_sync(0xffffffffu, ps1, 2);
        l0 = l0 * cr0 + ps0; m0 = mn0;
        l1 = l1 * cr1 + ps1; m1 = mn1;
        #pragma unroll
        for (int nt = 0; nt < 8; nt++) {
            o[nt][0] *= cr0; o[nt][1] *= cr0;
            o[nt][2] *= cr1; o[nt][3] *= cr1;
        }

        // ---- stage P split+packed (warp-private rows) ----
        #pragma unroll
        for (int nt = 0; nt < 8; nt++) {
            int c2 = nt * 4 + tg;
            uint32_t hw, lw;
            sp2(sc[nt][0], sc[nt][1], hw, lw);
            Ph[rowA * PADP + c2] = hw; Pl[rowA * PADP + c2] = lw;
            sp2(sc[nt][2], sc[nt][3], hw, lw);
            Ph[(rowA + 8) * PADP + c2] = hw; Pl[(rowA + 8) * PADP + c2] = lw;
        }
        __syncwarp();

        // ---- O += P V ----
        #pragma unroll
        for (int ks = 0; ks < 4; ks++) {
            uint32_t ah[4], al[4];
            ah[0] = Ph[ rowA      * PADP + ks * 8 + tg];
            ah[1] = Ph[(rowA + 8) * PADP + ks * 8 + tg];
            ah[2] = Ph[ rowA      * PADP + ks * 8 + tg + 4];
            ah[3] = Ph[(rowA + 8) * PADP + ks * 8 + tg + 4];
            al[0] = Pl[ rowA      * PADP + ks * 8 + tg];
            al[1] = Pl[(rowA + 8) * PADP + ks * 8 + tg];
            al[2] = Pl[ rowA      * PADP + ks * 8 + tg + 4];
            al[3] = Pl[(rowA + 8) * PADP + ks * 8 + tg + 4];
            #pragma unroll
            for (int nt = 0; nt < 8; nt++) {
                int n = nt * 8 + g;
                uint32_t b0h = Vh[(ks * 8 + tg)     * PADT + n];
                uint32_t b1h = Vh[(ks * 8 + tg + 4) * PADT + n];
                uint32_t b0l = Vl[(ks * 8 + tg)     * PADT + n];
                uint32_t b1l = Vl[(ks * 8 + tg + 4) * PADT + n];
                mma_bf16(o[nt], ah[0], ah[1], ah[2], ah[3], b0h, b1h);
                mma_bf16(o[nt], ah[0], ah[1], ah[2], ah[3], b0l, b1l);
                mma_bf16(o[nt], al[0], al[1], al[2], al[3], b0h, b1h);
            }
        }
    }

    // ---- epilogue: normalize + split-store to g_AVh/g_AVl ----
    float i0 = 1.f / l0, i1 = 1.f / l1;
    int sg0 = s0 + rowA, sg1 = sg0 + 8;
    #pragma unroll
    for (int nt = 0; nt < 8; nt++) {
        int c2 = h * 32 + nt * 4 + tg;
        uint32_t hw, lw;
        sp2(o[nt][0] * i0, o[nt][1] * i0, hw, lw);
        g_AVh[((size_t)sg0 * BATCH + b) * 512 + c2] = hw;
        g_AVl[((size_t)sg0 * BATCH + b) * 512 + c2] = lw;
        sp2(o[nt][2] * i1, o[nt][3] * i1, hw, lw);
        g_AVh[((size_t)sg1 * BATCH + b) * 512 + c2] = hw;
        g_AVl[((size_t)sg1 * BATCH + b) * 512 + c2] = lw;
    }
}

// ---------------------------------------------------------------------------
extern "C" void kernel_launch(void* const* d_in, const int* in_sizes, int n_in,
                              void* d_out, int out_size)
{
    const float* inputs = (const float*)d_in[0];
    const float* enc    = (const float*)d_in[2];
    const float* u      = (const float*)d_in[3];
    const unsigned char* mask = (const unsigned char*)d_in[5];
    const float* Wkv = (const float*)d_in[6];
    const float* bkv = (const float*)d_in[7];
    const float* Wq  = (const float*)d_in[8];
    const float* bq  = (const float*)d_in[9];
    const float* Wp  = (const float*)d_in[10];
    const float* bp  = (const float*)d_in[11];
    float* out = (float*)d_out;

    uint32_t *encH, *encL, *inH, *inL, *wkvH, *wkvL, *wqH, *wqL, *wpH, *wpL, *avH, *avL;
    cudaGetSymbolAddress((void**)&encH, g_encH); cudaGetSymbolAddress((void**)&encL, g_encL);
    cudaGetSymbolAddress((void**)&inH,  g_inH);  cudaGetSymbolAddress((void**)&inL,  g_inL);
    cudaGetSymbolAddress((void**)&wkvH, g_WkvH); cudaGetSymbolAddress((void**)&wkvL, g_WkvL);
    cudaGetSymbolAddress((void**)&wqH,  g_WqH);  cudaGetSymbolAddress((void**)&wqL,  g_WqL);
    cudaGetSymbolAddress((void**)&wpH,  g_WpH);  cudaGetSymbolAddress((void**)&wpL,  g_WpL);
    cudaGetSymbolAddress((void**)&avH,  g_AVh);  cudaGetSymbolAddress((void**)&avL,  g_AVl);

    const int ASMEM = (4 * 32 * PADT + 2 * 128 * PADP) * 4;   // 71680 B
    cudaFuncSetAttribute(attn_bf16, cudaFuncAttributeMaxDynamicSharedMemorySize, ASMEM);

    dim3 blk(256);
    // conversions (memory-bound, ~15us total)
    conv_b<<<1024, blk>>>(Wkv, wkvH, wkvL, 2048);
    conv_b<<<512,  blk>>>(Wq,  wqH,  wqL,  1024);
    conv_b<<<512,  blk>>>(Wp,  wpH,  wpL,  1024);
    conv_a<<<2048, blk>>>(enc,    encH, encL);
    conv_a<<<2048, blk>>>(inputs, inH,  inL);
    // projections
    mma_gemm<0><<<dim3(16, 32), blk>>>(encH, encL, wkvH, wkvL, bkv, nullptr, nullptr, 2 * HD);
    mma_gemm<1><<<dim3(8, 32),  blk>>>(inH,  inL,  wqH,  wqL,  bq,  u,       nullptr, HD);
    // attention
    attn_bf16<<<dim3(S_LEN / 128, BATCH * HEADS), blk, ASMEM>>>(mask);
    // output projection
    mma_gemm<2><<<dim3(8, 32),  blk>>>(avH, avL, wpH, wpL, bp, nullptr, out, HD);
}

// round 10
// speedup vs baseline: 1.0531x; 1.0531x over previous
#include <cuda_runtime.h>
#include <math.h>
#include <stdint.h>

#define S_LEN 2048
#define T_LEN 2048
#define BATCH 2
#define EDIM  1024
#define HEADS 16
#define HDIM  64
#define HD    (HEADS*HDIM)   /* 1024 */

// ---------------- scratch (static device globals; no allocation) ----------
__device__ uint32_t g_encH[4096*512], g_encL[4096*512];   // enc  (T*B, E/2)
__device__ uint32_t g_inH [4096*512], g_inL [4096*512];   // inp  (S*B, E/2)
__device__ uint32_t g_WkvH[512*2048], g_WkvL[512*2048];   // Wkv  (E/2, 2HD)
__device__ uint32_t g_WqH [512*1024], g_WqL [512*1024];   // Wq   (E/2, HD)
__device__ uint32_t g_WpH [512*1024], g_WpL [512*1024];   // Wp   (HD/2, E)
__device__ uint32_t g_Kh[BATCH*HEADS*T_LEN*32], g_Kl[BATCH*HEADS*T_LEN*32]; // (B,H,T,D/2)
__device__ uint32_t g_Qh[BATCH*HEADS*S_LEN*32], g_Ql[BATCH*HEADS*S_LEN*32]; // (B,H,S,D/2)
__device__ float    g_V [BATCH*HEADS*T_LEN*HDIM];                            // (B,H,T,D)
__device__ uint32_t g_AVh[4096*512], g_AVl[4096*512];     // (S*B, HD/2)
__device__ int      g_mflag[16*32];                       // per (s-block, j-tile)

// ---------------- bf16 split helpers ---------------------------------------
__device__ __forceinline__ uint32_t bfbits(float x) {
    uint32_t u = __float_as_uint(x);
    return (u + 0x7FFFu + ((u >> 16) & 1u)) & 0xFFFF0000u;
}
__device__ __forceinline__ void sp2(float e, float o, uint32_t& hw, uint32_t& lw) {
    uint32_t he = bfbits(e), ho = bfbits(o);
    float re = e - __uint_as_float(he);
    float ro = o - __uint_as_float(ho);
    hw = __byte_perm(he, ho, 0x7632);
    lw = __byte_perm(bfbits(re), bfbits(ro), 0x7632);
}
__device__ __forceinline__ void mma_bf16(float* c, uint32_t a0, uint32_t a1,
                                         uint32_t a2, uint32_t a3,
                                         uint32_t b0, uint32_t b1) {
    asm volatile(
        "mma.sync.aligned.m16n8k16.row.col.f32.bf16.bf16.f32 "
        "{%0,%1,%2,%3}, {%4,%5,%6,%7}, {%8,%9}, {%0,%1,%2,%3};"
        : "+f"(c[0]), "+f"(c[1]), "+f"(c[2]), "+f"(c[3])
        : "r"(a0), "r"(a1), "r"(a2), "r"(a3), "r"(b0), "r"(b1));
}

// ===========================================================================
// conversion kernels
// ===========================================================================
__global__ __launch_bounds__(256) void conv_b(const float* __restrict__ W,
                                              uint32_t* __restrict__ Wh,
                                              uint32_t* __restrict__ Wl, int N) {
    int idx = blockIdx.x * 256 + threadIdx.x;
    int k2 = idx / (N / 4), n4 = (idx % (N / 4)) * 4;
    const float* r0 = W + (size_t)(2 * k2) * N + n4;
    float4 a = *(const float4*)r0;
    float4 b = *(const float4*)(r0 + N);
    uint4 h, l;
    sp2(a.x, b.x, h.x, l.x); sp2(a.y, b.y, h.y, l.y);
    sp2(a.z, b.z, h.z, l.z); sp2(a.w, b.w, h.w, l.w);
    *(uint4*)(Wh + (size_t)k2 * N + n4) = h;
    *(uint4*)(Wl + (size_t)k2 * N + n4) = l;
}
__global__ __launch_bounds__(256) void conv_a(const float* __restrict__ A,
                                              uint32_t* __restrict__ Ah,
                                              uint32_t* __restrict__ Al) {
    int idx = blockIdx.x * 256 + threadIdx.x;
    int m = idx >> 7, c8 = (idx & 127) * 8;
    float4 f0 = *(const float4*)(A + (size_t)m * 1024 + c8);
    float4 f1 = *(const float4*)(A + (size_t)m * 1024 + c8 + 4);
    uint4 h, l;
    sp2(f0.x, f0.y, h.x, l.x); sp2(f0.z, f0.w, h.y, l.y);
    sp2(f1.x, f1.y, h.z, l.z); sp2(f1.z, f1.w, h.w, l.w);
    *(uint4*)(Ah + (size_t)m * 512 + c8 / 2) = h;
    *(uint4*)(Al + (size_t)m * 512 + c8 / 2) = l;
}
// mask tile-flag pre-scan: grid (16, 32), flag per (128-row block, 64-col tile)
__global__ __launch_bounds__(256) void mask_scan(const unsigned char* __restrict__ mask) {
    const unsigned char* base = mask + (size_t)(blockIdx.x * 128) * T_LEN + blockIdx.y * 64;
    uint32_t m = 0;
    #pragma unroll
    for (int it = 0; it < 2; it++) {
        int idx = threadIdx.x + it * 256;
        int r = idx >> 2, c16 = (idx & 3) * 16;
        uint4 v = *(const uint4*)(base + (size_t)r * T_LEN + c16);
        m |= v.x | v.y | v.z | v.w;
    }
    int any = __syncthreads_or((int)m);
    if (threadIdx.x == 0) g_mflag[blockIdx.x * 32 + blockIdx.y] = any;
}

// ===========================================================================
// 3x-bf16 GEMM on pre-split operands (unchanged from R9).
// ===========================================================================
#define PADM 136

template<int MODE>
__global__ __launch_bounds__(256) void mma_gemm(
    const uint32_t* __restrict__ Ahg, const uint32_t* __restrict__ Alg,
    const uint32_t* __restrict__ Bhg, const uint32_t* __restrict__ Blg,
    const float* __restrict__ bias, const float* __restrict__ u,
    float* __restrict__ out, int N)
{
    __shared__ uint32_t Ah[2][8][PADM], Al[2][8][PADM];
    __shared__ uint32_t Bh[2][8][PADM], Bl[2][8][PADM];

    const int tid  = threadIdx.x;
    const int wid  = tid >> 5, lane = tid & 31;
    const int g    = lane >> 2, tg = lane & 3;
    const int wm   = wid >> 2,  wn = wid & 3;
    const int m0   = blockIdx.y * 128, n0 = blockIdx.x * 128;

    const int aRow = tid >> 2;
    const int aKp  = (tid & 3) * 2;
    const int bKp  = tid >> 5;
    const int bCol = (tid & 31) * 4;

    float acc[4][4][4] = {};

    uint2 ah0, ah1, al0, al1;
    uint4 bh4, bl4;
    #define GLOAD(k2) do { \
        ah0 = *(const uint2*)(Ahg + (size_t)(m0 + aRow)      * 512 + (k2) + aKp); \
        ah1 = *(const uint2*)(Ahg + (size_t)(m0 + aRow + 64) * 512 + (k2) + aKp); \
        al0 = *(const uint2*)(Alg + (size_t)(m0 + aRow)      * 512 + (k2) + aKp); \
        al1 = *(const uint2*)(Alg + (size_t)(m0 + aRow + 64) * 512 + (k2) + aKp); \
        bh4 = *(const uint4*)(Bhg + (size_t)((k2) + bKp) * N + n0 + bCol); \
        bl4 = *(const uint4*)(Blg + (size_t)((k2) + bKp) * N + n0 + bCol); \
    } while (0)
    #define SSTORE(buf) do { \
        Ah[buf][aKp][aRow]          = ah0.x; Ah[buf][aKp + 1][aRow]          = ah0.y; \
        Ah[buf][aKp][aRow + 64]     = ah1.x; Ah[buf][aKp + 1][aRow + 64]     = ah1.y; \
        Al[buf][aKp][aRow]          = al0.x; Al[buf][aKp + 1][aRow]          = al0.y; \
        Al[buf][aKp][aRow + 64]     = al1.x; Al[buf][aKp + 1][aRow + 64]     = al1.y; \
        *(uint4*)&Bh[buf][bKp][bCol] = bh4; \
        *(uint4*)&Bl[buf][bKp][bCol] = bl4; \
    } while (0)

    GLOAD(0);
    SSTORE(0);
    __syncthreads();

    const int NKB = 64;
    for (int kb = 0; kb < NKB; kb++) {
        int buf = kb & 1;
        if (kb + 1 < NKB) GLOAD((kb + 1) * 8);

        uint32_t ah[4][4], al4[4][4];
        #pragma unroll
        for (int mt = 0; mt < 4; mt++) {
            int r = wm * 64 + mt * 16 + g;
            ah[mt][0]  = Ah[buf][tg][r];
            ah[mt][1]  = Ah[buf][tg][r + 8];
            ah[mt][2]  = Ah[buf][tg + 4][r];
            ah[mt][3]  = Ah[buf][tg + 4][r + 8];
            al4[mt][0] = Al[buf][tg][r];
            al4[mt][1] = Al[buf][tg][r + 8];
            al4[mt][2] = Al[buf][tg + 4][r];
            al4[mt][3] = Al[buf][tg + 4][r + 8];
        }
        uint32_t bh[4][2], bl4r[4][2];
        #pragma unroll
        for (int nt = 0; nt < 4; nt++) {
            int c = wn * 32 + nt * 8 + g;
            bh[nt][0]   = Bh[buf][tg][c];
            bh[nt][1]   = Bh[buf][tg + 4][c];
            bl4r[nt][0] = Bl[buf][tg][c];
            bl4r[nt][1] = Bl[buf][tg + 4][c];
        }
        #pragma unroll
        for (int mt = 0; mt < 4; mt++)
            #pragma unroll
            for (int nt = 0; nt < 4; nt++) {
                float* c = acc[mt][nt];
                mma_bf16(c, ah[mt][0], ah[mt][1], ah[mt][2], ah[mt][3],
                            bh[nt][0], bh[nt][1]);
                mma_bf16(c, ah[mt][0], ah[mt][1], ah[mt][2], ah[mt][3],
                            bl4r[nt][0], bl4r[nt][1]);
                mma_bf16(c, al4[mt][0], al4[mt][1], al4[mt][2], al4[mt][3],
                            bh[nt][0], bh[nt][1]);
            }

        if (kb + 1 < NKB) SSTORE(1 - buf);
        __syncthreads();
    }
    #undef GLOAD
    #undef SSTORE

    #pragma unroll
    for (int mt = 0; mt < 4; mt++) {
        #pragma unroll
        for (int nt = 0; nt < 4; nt++) {
            int n  = n0 + wn * 32 + nt * 8 + tg * 2;
            int mA = m0 + wm * 64 + mt * 16 + g;
            float bs0 = __ldg(bias + n), bs1 = __ldg(bias + n + 1);
            float v00 = acc[mt][nt][0] + bs0;
            float v01 = acc[mt][nt][1] + bs1;
            float v10 = acc[mt][nt][2] + bs0;
            float v11 = acc[mt][nt][3] + bs1;
            int t0 = mA >> 1, bb = mA & 1;
            int t1 = (mA + 8) >> 1;
            if (MODE == 0) {
                if (n < HD) {
                    int h = n >> 6, d2 = (n & 63) >> 1;
                    size_t base = ((size_t)(bb * HEADS + h)) * T_LEN;
                    uint32_t hw, lw;
                    sp2(v00, v01, hw, lw);
                    g_Kh[(base + t0) * 32 + d2] = hw;
                    g_Kl[(base + t0) * 32 + d2] = lw;
                    sp2(v10, v11, hw, lw);
                    g_Kh[(base + t1) * 32 + d2] = hw;
                    g_Kl[(base + t1) * 32 + d2] = lw;
                } else {
                    int nn = n - HD;
                    int h = nn >> 6, d = nn & 63;
                    size_t base = (((size_t)(bb * HEADS + h)) * T_LEN) * HDIM + d;
                    g_V[base + (size_t)t0 * HDIM]     = v00;
                    g_V[base + (size_t)t0 * HDIM + 1] = v01;
                    g_V[base + (size_t)t1 * HDIM]     = v10;
                    g_V[base + (size_t)t1 * HDIM + 1] = v11;
                }
            } else if (MODE == 1) {
                float u0 = __ldg(u + n), u1 = __ldg(u + n + 1);
                int h = n >> 6, d2 = (n & 63) >> 1;
                size_t base = ((size_t)(bb * HEADS + h)) * S_LEN;
                uint32_t hw, lw;
                sp2(v00 + u0, v01 + u1, hw, lw);
                g_Qh[(base + t0) * 32 + d2] = hw;
                g_Ql[(base + t0) * 32 + d2] = lw;
                sp2(v10 + u0, v11 + u1, hw, lw);
                g_Qh[(base + t1) * 32 + d2] = hw;
                g_Ql[(base + t1) * 32 + d2] = lw;
            } else {
                out[(size_t)mA * EDIM + n]           = v00;
                out[(size_t)mA * EDIM + n + 1]       = v01;
                out[(size_t)(mA + 8) * EDIM + n]     = v10;
                out[(size_t)(mA + 8) * EDIM + n + 1] = v11;
            }
        }
    }
}

// ===========================================================================
// Flash attention, 3x-bf16. PADT=72 (conflict-free frag reads), rotated K
// stores (conflict-free writes), mask tile-flags, 2 CTAs/SM.
// ===========================================================================
#define PADT 72
#define PADP 36

__global__ __launch_bounds__(256, 2) void attn_bf16(const unsigned char* __restrict__ mask)
{
    extern __shared__ uint32_t smu[];
    uint32_t* Kh = smu;
    uint32_t* Kl = Kh + 32 * PADT;
    uint32_t* Vh = Kl + 32 * PADT;
    uint32_t* Vl = Vh + 32 * PADT;
    uint32_t* Ph = Vl + 32 * PADT;
    uint32_t* Pl = Ph + 128 * PADP;

    const int bh = blockIdx.y;
    const int b  = bh >> 4;
    const int h  = bh & 15;
    const int s0 = blockIdx.x * 128;
    const int tid = threadIdx.x;
    const int wid = tid >> 5, lane = tid & 31;
    const int g   = lane >> 2, tg = lane & 3;
    const int rowA = wid * 16 + g;

    const uint32_t* Khg = g_Kh + (size_t)bh * T_LEN * 32;
    const uint32_t* Klg = g_Kl + (size_t)bh * T_LEN * 32;
    const float*    Vg  = g_V  + (size_t)bh * T_LEN * HDIM;

    // K-loader geometry: kr = row 0..63, kq = d2 base {0,8,16,24}, kt = q8/8
    const int kr = tid >> 2;
    const int kt = tid & 3;
    const int kq = kt * 8;

    // ---- Q fragments: direct pre-split loads ----
    uint32_t qh[4][4], ql[4][4];
    {
        const uint32_t* qh0 = g_Qh + ((size_t)bh * S_LEN + s0 + rowA) * 32;
        const uint32_t* qh1 = qh0 + 8 * 32;
        const uint32_t* ql0 = g_Ql + ((size_t)bh * S_LEN + s0 + rowA) * 32;
        const uint32_t* ql1 = ql0 + 8 * 32;
        #pragma unroll
        for (int ks = 0; ks < 4; ks++) {
            qh[ks][0] = qh0[ks * 8 + tg];
            qh[ks][1] = qh1[ks * 8 + tg];
            qh[ks][2] = qh0[ks * 8 + tg + 4];
            qh[ks][3] = qh1[ks * 8 + tg + 4];
            ql[ks][0] = ql0[ks * 8 + tg];
            ql[ks][1] = ql1[ks * 8 + tg];
            ql[ks][2] = ql0[ks * 8 + tg + 4];
            ql[ks][3] = ql1[ks * 8 + tg + 4];
        }
    }

    float o[8][4] = {};
    float m0 = -1e30f, m1 = -1e30f, l0 = 0.f, l1 = 0.f;

    for (int j0 = 0; j0 < T_LEN; j0 += 64) {
        __syncthreads();

        // ---- K loader: u32 copy + transpose, rotated store order ----
        {
            uint32_t kw[8], lw[8];
            *(uint4*)&kw[0] = *(const uint4*)(Khg + (size_t)(j0 + kr) * 32 + kq);
            *(uint4*)&kw[4] = *(const uint4*)(Khg + (size_t)(j0 + kr) * 32 + kq + 4);
            *(uint4*)&lw[0] = *(const uint4*)(Klg + (size_t)(j0 + kr) * 32 + kq);
            *(uint4*)&lw[4] = *(const uint4*)(Klg + (size_t)(j0 + kr) * 32 + kq + 4);
            #pragma unroll
            for (int i = 0; i < 8; i++) {
                int j = (i + kt) & 7;                  // rotation kills write conflicts
                Kh[(kq + j) * PADT + kr] = kw[j];
                Kl[(kq + j) * PADT + kr] = lw[j];
            }
        }
        // ---- V loader: fp32 + split (pairs along t) ----
        #pragma unroll
        for (int it = 0; it < 2; it++) {
            int idx = tid + it * 256;
            int r2 = idx >> 4, c = (idx & 15) * 4;
            float4 va = *(const float4*)(Vg + (size_t)(j0 + 2 * r2)     * HDIM + c);
            float4 vb = *(const float4*)(Vg + (size_t)(j0 + 2 * r2 + 1) * HDIM + c);
            uint4 wh, wl;
            sp2(va.x, vb.x, wh.x, wl.x);
            sp2(va.y, vb.y, wh.y, wl.y);
            sp2(va.z, vb.z, wh.z, wl.z);
            sp2(va.w, vb.w, wh.w, wl.w);
            *(uint4*)&Vh[r2 * PADT + c] = wh;
            *(uint4*)&Vl[r2 * PADT + c] = wl;
        }
        int any_mask = g_mflag[blockIdx.x * 32 + (j0 >> 6)];
        __syncthreads();

        // ---- S = Q K^T ----
        float sc[8][4] = {};
        #pragma unroll
        for (int ks = 0; ks < 4; ks++) {
            #pragma unroll
            for (int nt = 0; nt < 8; nt++) {
                int n = nt * 8 + g;
                uint32_t b0h = Kh[(ks * 8 + tg)     * PADT + n];
                uint32_t b1h = Kh[(ks * 8 + tg + 4) * PADT + n];
                uint32_t b0l = Kl[(ks * 8 + tg)     * PADT + n];
                uint32_t b1l = Kl[(ks * 8 + tg + 4) * PADT + n];
                mma_bf16(sc[nt], qh[ks][0], qh[ks][1], qh[ks][2], qh[ks][3], b0h, b1h);
                mma_bf16(sc[nt], qh[ks][0], qh[ks][1], qh[ks][2], qh[ks][3], b0l, b1l);
                mma_bf16(sc[nt], ql[ks][0], ql[ks][1], ql[ks][2], ql[ks][3], b0h, b1h);
            }
        }

        #pragma unroll
        for (int nt = 0; nt < 8; nt++) {
            sc[nt][0] *= 0.125f; sc[nt][1] *= 0.125f;
            sc[nt][2] *= 0.125f; sc[nt][3] *= 0.125f;
        }
        if (any_mask) {
            int sg0 = s0 + rowA, sg1 = sg0 + 8;
            #pragma unroll
            for (int nt = 0; nt < 8; nt++) {
                int cg = j0 + nt * 8 + tg * 2;
                const unsigned char* m0p = mask + (size_t)sg0 * T_LEN + cg;
                const unsigned char* m1p = mask + (size_t)sg1 * T_LEN + cg;
                if (m0p[0]) sc[nt][0] = -INFINITY;
                if (m0p[1]) sc[nt][1] = -INFINITY;
                if (m1p[0]) sc[nt][2] = -INFINITY;
                if (m1p[1]) sc[nt][3] = -INFINITY;
            }
        }

        // ---- warp-local online softmax ----
        float mx0 = -1e30f, mx1 = -1e30f;
        #pragma unroll
        for (int nt = 0; nt < 8; nt++) {
            mx0 = fmaxf(mx0, fmaxf(sc[nt][0], sc[nt][1]));
            mx1 = fmaxf(mx1, fmaxf(sc[nt][2], sc[nt][3]));
        }
        mx0 = fmaxf(mx0, __shfl_xor_sync(0xffffffffu, mx0, 1));
        mx0 = fmaxf(mx0, __shfl_xor_sync(0xffffffffu, mx0, 2));
        mx1 = fmaxf(mx1, __shfl_xor_sync(0xffffffffu, mx1, 1));
        mx1 = fmaxf(mx1, __shfl_xor_sync(0xffffffffu, mx1, 2));

        float mn0 = fmaxf(m0, mx0), mn1 = fmaxf(m1, mx1);
        float cr0 = __expf(m0 - mn0), cr1 = __expf(m1 - mn1);
        float ps0 = 0.f, ps1 = 0.f;
        #pragma unroll
        for (int nt = 0; nt < 8; nt++) {
            sc[nt][0] = __expf(sc[nt][0] - mn0);
            sc[nt][1] = __expf(sc[nt][1] - mn0);
            sc[nt][2] = __expf(sc[nt][2] - mn1);
            sc[nt][3] = __expf(sc[nt][3] - mn1);
            ps0 += sc[nt][0] + sc[nt][1];
            ps1 += sc[nt][2] + sc[nt][3];
        }
        ps0 += __shfl_xor_sync(0xffffffffu, ps0, 1);
        ps0 += __shfl_xor_sync(0xffffffffu, ps0, 2);
        ps1 += __shfl_xor_sync(0xffffffffu, ps1, 1);
        ps1 += __shfl_xor_sync(0xffffffffu, ps1, 2);
        l0 = l0 * cr0 + ps0; m0 = mn0;
        l1 = l1 * cr1 + ps1; m1 = mn1;
        #pragma unroll
        for (int nt = 0; nt < 8; nt++) {
            o[nt][0] *= cr0; o[nt][1] *= cr0;
            o[nt][2] *= cr1; o[nt][3] *= cr1;
        }

        // ---- stage P split+packed (warp-private rows) ----
        #pragma unroll
        for (int nt = 0; nt < 8; nt++) {
            int c2 = nt * 4 + tg;
            uint32_t hw, lw;
            sp2(sc[nt][0], sc[nt][1], hw, lw);
            Ph[rowA * PADP + c2] = hw; Pl[rowA * PADP + c2] = lw;
            sp2(sc[nt][2], sc[nt][3], hw, lw);
            Ph[(rowA + 8) * PADP + c2] = hw; Pl[(rowA + 8) * PADP + c2] = lw;
        }
        __syncwarp();

        // ---- O += P V ----
        #pragma unroll
        for (int ks = 0; ks < 4; ks++) {
            uint32_t ah[4], al[4];
            ah[0] = Ph[ rowA      * PADP + ks * 8 + tg];
            ah[1] = Ph[(rowA + 8) * PADP + ks * 8 + tg];
            ah[2] = Ph[ rowA      * PADP + ks * 8 + tg + 4];
            ah[3] = Ph[(rowA + 8) * PADP + ks * 8 + tg + 4];
            al[0] = Pl[ rowA      * PADP + ks * 8 + tg];
            al[1] = Pl[(rowA + 8) * PADP + ks * 8 + tg];
            al[2] = Pl[ rowA      * PADP + ks * 8 + tg + 4];
            al[3] = Pl[(rowA + 8) * PADP + ks * 8 + tg + 4];
            #pragma unroll
            for (int nt = 0; nt < 8; nt++) {
                int n = nt * 8 + g;
                uint32_t b0h = Vh[(ks * 8 + tg)     * PADT + n];
                uint32_t b1h = Vh[(ks * 8 + tg + 4) * PADT + n];
                uint32_t b0l = Vl[(ks * 8 + tg)     * PADT + n];
                uint32_t b1l = Vl[(ks * 8 + tg + 4) * PADT + n];
                mma_bf16(o[nt], ah[0], ah[1], ah[2], ah[3], b0h, b1h);
                mma_bf16(o[nt], ah[0], ah[1], ah[2], ah[3], b0l, b1l);
                mma_bf16(o[nt], al[0], al[1], al[2], al[3], b0h, b1h);
            }
        }
    }

    // ---- epilogue: normalize + split-store to g_AVh/g_AVl ----
    float i0 = 1.f / l0, i1 = 1.f / l1;
    int sg0 = s0 + rowA, sg1 = sg0 + 8;
    #pragma unroll
    for (int nt = 0; nt < 8; nt++) {
        int c2 = h * 32 + nt * 4 + tg;
        uint32_t hw, lw;
        sp2(o[nt][0] * i0, o[nt][1] * i0, hw, lw);
        g_AVh[((size_t)sg0 * BATCH + b) * 512 + c2] = hw;
        g_AVl[((size_t)sg0 * BATCH + b) * 512 + c2] = lw;
        sp2(o[nt][2] * i1, o[nt][3] * i1, hw, lw);
        g_AVh[((size_t)sg1 * BATCH + b) * 512 + c2] = hw;
        g_AVl[((size_t)sg1 * BATCH + b) * 512 + c2] = lw;
    }
}

// ---------------------------------------------------------------------------
extern "C" void kernel_launch(void* const* d_in, const int* in_sizes, int n_in,
                              void* d_out, int out_size)
{
    const float* inputs = (const float*)d_in[0];
    const float* enc    = (const float*)d_in[2];
    const float* u      = (const float*)d_in[3];
    const unsigned char* mask = (const unsigned char*)d_in[5];
    const float* Wkv = (const float*)d_in[6];
    const float* bkv = (const float*)d_in[7];
    const float* Wq  = (const float*)d_in[8];
    const float* bq  = (const float*)d_in[9];
    const float* Wp  = (const float*)d_in[10];
    const float* bp  = (const float*)d_in[11];
    float* out = (float*)d_out;

    uint32_t *encH, *encL, *inH, *inL, *wkvH, *wkvL, *wqH, *wqL, *wpH, *wpL, *avH, *avL;
    cudaGetSymbolAddress((void**)&encH, g_encH); cudaGetSymbolAddress((void**)&encL, g_encL);
    cudaGetSymbolAddress((void**)&inH,  g_inH);  cudaGetSymbolAddress((void**)&inL,  g_inL);
    cudaGetSymbolAddress((void**)&wkvH, g_WkvH); cudaGetSymbolAddress((void**)&wkvL, g_WkvL);
    cudaGetSymbolAddress((void**)&wqH,  g_WqH);  cudaGetSymbolAddress((void**)&wqL,  g_WqL);
    cudaGetSymbolAddress((void**)&wpH,  g_WpH);  cudaGetSymbolAddress((void**)&wpL,  g_WpL);
    cudaGetSymbolAddress((void**)&avH,  g_AVh);  cudaGetSymbolAddress((void**)&avL,  g_AVl);

    const int ASMEM = (4 * 32 * PADT + 2 * 128 * PADP) * 4;   // 73728 B
    cudaFuncSetAttribute(attn_bf16, cudaFuncAttributeMaxDynamicSharedMemorySize, ASMEM);

    dim3 blk(256);
    // conversions + mask pre-scan
    conv_b<<<1024, blk>>>(Wkv, wkvH, wkvL, 2048);
    conv_b<<<512,  blk>>>(Wq,  wqH,  wqL,  1024);
    conv_b<<<512,  blk>>>(Wp,  wpH,  wpL,  1024);
    conv_a<<<2048, blk>>>(enc,    encH, encL);
    conv_a<<<2048, blk>>>(inputs, inH,  inL);
    mask_scan<<<dim3(16, 32), blk>>>(mask);
    // projections
    mma_gemm<0><<<dim3(16, 32), blk>>>(encH, encL, wkvH, wkvL, bkv, nullptr, nullptr, 2 * HD);
    mma_gemm<1><<<dim3(8, 32),  blk>>>(inH,  inL,  wqH,  wqL,  bq,  u,       nullptr, HD);
    // attention
    attn_bf16<<<dim3(S_LEN / 128, BATCH * HEADS), blk, ASMEM>>>(mask);
    // output projection
    mma_gemm<2><<<dim3(8, 32),  blk>>>(avH, avL, wpH, wpL, bp, nullptr, out, HD);
}

// round 11
// speedup vs baseline: 1.1505x; 1.0925x over previous
#include <cuda_runtime.h>
#include <math.h>
#include <stdint.h>

#define S_LEN 2048
#define T_LEN 2048
#define BATCH 2
#define EDIM  1024
#define HEADS 16
#define HDIM  64
#define HD    (HEADS*HDIM)   /* 1024 */

// ---------------- scratch (static device globals; no allocation) ----------
__device__ uint32_t g_encH[4096*512], g_encL[4096*512];   // enc  (T*B, E/2)
__device__ uint32_t g_inH [4096*512], g_inL [4096*512];   // inp  (S*B, E/2)
__device__ uint32_t g_WkvH[512*2048], g_WkvL[512*2048];   // Wkv  (E/2, 2HD)
__device__ uint32_t g_WqH [512*1024], g_WqL [512*1024];   // Wq   (E/2, HD)
__device__ uint32_t g_WpH [512*1024], g_WpL [512*1024];   // Wp   (HD/2, E)
__device__ uint32_t g_KhT[BATCH*HEADS*32*T_LEN], g_KlT[BATCH*HEADS*32*T_LEN]; // (B,H,D/2,T)
__device__ uint32_t g_Qh[BATCH*HEADS*S_LEN*32], g_Ql[BATCH*HEADS*S_LEN*32];   // (B,H,S,D/2)
__device__ float    g_V [BATCH*HEADS*T_LEN*HDIM];                              // (B,H,T,D)
__device__ uint32_t g_Vh2[BATCH*HEADS*(T_LEN/2)*HDIM], g_Vl2[BATCH*HEADS*(T_LEN/2)*HDIM]; // (B,H,T/2,D)
__device__ uint32_t g_AVh[4096*512], g_AVl[4096*512];     // (S*B, HD/2)
__device__ int      g_mflag[16*32];                       // per (s-block, j-tile)

// ---------------- bf16 split helpers ---------------------------------------
__device__ __forceinline__ uint32_t bfbits(float x) {
    uint32_t u = __float_as_uint(x);
    return (u + 0x7FFFu + ((u >> 16) & 1u)) & 0xFFFF0000u;
}
__device__ __forceinline__ void sp2(float e, float o, uint32_t& hw, uint32_t& lw) {
    uint32_t he = bfbits(e), ho = bfbits(o);
    float re = e - __uint_as_float(he);
    float ro = o - __uint_as_float(ho);
    hw = __byte_perm(he, ho, 0x7632);
    lw = __byte_perm(bfbits(re), bfbits(ro), 0x7632);
}
__device__ __forceinline__ void mma_bf16(float* c, uint32_t a0, uint32_t a1,
                                         uint32_t a2, uint32_t a3,
                                         uint32_t b0, uint32_t b1) {
    asm volatile(
        "mma.sync.aligned.m16n8k16.row.col.f32.bf16.bf16.f32 "
        "{%0,%1,%2,%3}, {%4,%5,%6,%7}, {%8,%9}, {%0,%1,%2,%3};"
        : "+f"(c[0]), "+f"(c[1]), "+f"(c[2]), "+f"(c[3])
        : "r"(a0), "r"(a1), "r"(a2), "r"(a3), "r"(b0), "r"(b1));
}
__device__ __forceinline__ uint32_t smem_u32(const void* p) {
    uint32_t a;
    asm("{ .reg .u64 t; cvta.to.shared.u64 t, %1; cvt.u32.u64 %0, t; }"
        : "=r"(a) : "l"(p));
    return a;
}
__device__ __forceinline__ void cpa16(uint32_t dst, const uint32_t* src) {
    asm volatile("cp.async.cg.shared.global [%0], [%1], 16;"
                 :: "r"(dst), "l"(src) : "memory");
}
#define CP_COMMIT() asm volatile("cp.async.commit_group;" ::: "memory")

// ===========================================================================
// conversion kernels
// ===========================================================================
__global__ __launch_bounds__(256) void conv_b(const float* __restrict__ W,
                                              uint32_t* __restrict__ Wh,
                                              uint32_t* __restrict__ Wl, int N) {
    int idx = blockIdx.x * 256 + threadIdx.x;
    int k2 = idx / (N / 4), n4 = (idx % (N / 4)) * 4;
    const float* r0 = W + (size_t)(2 * k2) * N + n4;
    float4 a = *(const float4*)r0;
    float4 b = *(const float4*)(r0 + N);
    uint4 h, l;
    sp2(a.x, b.x, h.x, l.x); sp2(a.y, b.y, h.y, l.y);
    sp2(a.z, b.z, h.z, l.z); sp2(a.w, b.w, h.w, l.w);
    *(uint4*)(Wh + (size_t)k2 * N + n4) = h;
    *(uint4*)(Wl + (size_t)k2 * N + n4) = l;
}
__global__ __launch_bounds__(256) void conv_a(const float* __restrict__ A,
                                              uint32_t* __restrict__ Ah,
                                              uint32_t* __restrict__ Al) {
    int idx = blockIdx.x * 256 + threadIdx.x;
    int m = idx >> 7, c8 = (idx & 127) * 8;
    float4 f0 = *(const float4*)(A + (size_t)m * 1024 + c8);
    float4 f1 = *(const float4*)(A + (size_t)m * 1024 + c8 + 4);
    uint4 h, l;
    sp2(f0.x, f0.y, h.x, l.x); sp2(f0.z, f0.w, h.y, l.y);
    sp2(f1.x, f1.y, h.z, l.z); sp2(f1.z, f1.w, h.w, l.w);
    *(uint4*)(Ah + (size_t)m * 512 + c8 / 2) = h;
    *(uint4*)(Al + (size_t)m * 512 + c8 / 2) = l;
}
// V fp32 (B,H,T,D) -> pre-split t-paired (B,H,T/2,D) u32
__global__ __launch_bounds__(256) void conv_v() {
    int idx = blockIdx.x * 256 + threadIdx.x;
    int bt2 = idx >> 4;
    int c4  = (idx & 15) * 4;
    const float* src = g_V + (size_t)bt2 * 2 * HDIM + c4;
    float4 a = *(const float4*)src;
    float4 b = *(const float4*)(src + HDIM);
    uint4 h, l;
    sp2(a.x, b.x, h.x, l.x); sp2(a.y, b.y, h.y, l.y);
    sp2(a.z, b.z, h.z, l.z); sp2(a.w, b.w, h.w, l.w);
    *(uint4*)(g_Vh2 + (size_t)bt2 * HDIM + c4) = h;
    *(uint4*)(g_Vl2 + (size_t)bt2 * HDIM + c4) = l;
}
// mask tile-flag pre-scan
__global__ __launch_bounds__(256) void mask_scan(const unsigned char* __restrict__ mask) {
    const unsigned char* base = mask + (size_t)(blockIdx.x * 128) * T_LEN + blockIdx.y * 64;
    uint32_t m = 0;
    #pragma unroll
    for (int it = 0; it < 2; it++) {
        int idx = threadIdx.x + it * 256;
        int r = idx >> 2, c16 = (idx & 3) * 16;
        uint4 v = *(const uint4*)(base + (size_t)r * T_LEN + c16);
        m |= v.x | v.y | v.z | v.w;
    }
    int any = __syncthreads_or((int)m);
    if (threadIdx.x == 0) g_mflag[blockIdx.x * 32 + blockIdx.y] = any;
}

// ===========================================================================
// 3x-bf16 GEMM on pre-split operands (R9 mainloop; K now stored transposed).
// ===========================================================================
#define PADM 136

template<int MODE>
__global__ __launch_bounds__(256) void mma_gemm(
    const uint32_t* __restrict__ Ahg, const uint32_t* __restrict__ Alg,
    const uint32_t* __restrict__ Bhg, const uint32_t* __restrict__ Blg,
    const float* __restrict__ bias, const float* __restrict__ u,
    float* __restrict__ out, int N)
{
    __shared__ uint32_t Ah[2][8][PADM], Al[2][8][PADM];
    __shared__ uint32_t Bh[2][8][PADM], Bl[2][8][PADM];

    const int tid  = threadIdx.x;
    const int wid  = tid >> 5, lane = tid & 31;
    const int g    = lane >> 2, tg = lane & 3;
    const int wm   = wid >> 2,  wn = wid & 3;
    const int m0   = blockIdx.y * 128, n0 = blockIdx.x * 128;

    const int aRow = tid >> 2;
    const int aKp  = (tid & 3) * 2;
    const int bKp  = tid >> 5;
    const int bCol = (tid & 31) * 4;

    float acc[4][4][4] = {};

    uint2 ah0, ah1, al0, al1;
    uint4 bh4, bl4;
    #define GLOAD(k2) do { \
        ah0 = *(const uint2*)(Ahg + (size_t)(m0 + aRow)      * 512 + (k2) + aKp); \
        ah1 = *(const uint2*)(Ahg + (size_t)(m0 + aRow + 64) * 512 + (k2) + aKp); \
        al0 = *(const uint2*)(Alg + (size_t)(m0 + aRow)      * 512 + (k2) + aKp); \
        al1 = *(const uint2*)(Alg + (size_t)(m0 + aRow + 64) * 512 + (k2) + aKp); \
        bh4 = *(const uint4*)(Bhg + (size_t)((k2) + bKp) * N + n0 + bCol); \
        bl4 = *(const uint4*)(Blg + (size_t)((k2) + bKp) * N + n0 + bCol); \
    } while (0)
    #define SSTORE(buf) do { \
        Ah[buf][aKp][aRow]          = ah0.x; Ah[buf][aKp + 1][aRow]          = ah0.y; \
        Ah[buf][aKp][aRow + 64]     = ah1.x; Ah[buf][aKp + 1][aRow + 64]     = ah1.y; \
        Al[buf][aKp][aRow]          = al0.x; Al[buf][aKp + 1][aRow]          = al0.y; \
        Al[buf][aKp][aRow + 64]     = al1.x; Al[buf][aKp + 1][aRow + 64]     = al1.y; \
        *(uint4*)&Bh[buf][bKp][bCol] = bh4; \
        *(uint4*)&Bl[buf][bKp][bCol] = bl4; \
    } while (0)

    GLOAD(0);
    SSTORE(0);
    __syncthreads();

    const int NKB = 64;
    for (int kb = 0; kb < NKB; kb++) {
        int buf = kb & 1;
        if (kb + 1 < NKB) GLOAD((kb + 1) * 8);

        uint32_t ah[4][4], al4[4][4];
        #pragma unroll
        for (int mt = 0; mt < 4; mt++) {
            int r = wm * 64 + mt * 16 + g;
            ah[mt][0]  = Ah[buf][tg][r];
            ah[mt][1]  = Ah[buf][tg][r + 8];
            ah[mt][2]  = Ah[buf][tg + 4][r];
            ah[mt][3]  = Ah[buf][tg + 4][r + 8];
            al4[mt][0] = Al[buf][tg][r];
            al4[mt][1] = Al[buf][tg][r + 8];
            al4[mt][2] = Al[buf][tg + 4][r];
            al4[mt][3] = Al[buf][tg + 4][r + 8];
        }
        uint32_t bh[4][2], bl4r[4][2];
        #pragma unroll
        for (int nt = 0; nt < 4; nt++) {
            int c = wn * 32 + nt * 8 + g;
            bh[nt][0]   = Bh[buf][tg][c];
            bh[nt][1]   = Bh[buf][tg + 4][c];
            bl4r[nt][0] = Bl[buf][tg][c];
            bl4r[nt][1] = Bl[buf][tg + 4][c];
        }
        #pragma unroll
        for (int mt = 0; mt < 4; mt++)
            #pragma unroll
            for (int nt = 0; nt < 4; nt++) {
                float* c = acc[mt][nt];
                mma_bf16(c, ah[mt][0], ah[mt][1], ah[mt][2], ah[mt][3],
                            bh[nt][0], bh[nt][1]);
                mma_bf16(c, ah[mt][0], ah[mt][1], ah[mt][2], ah[mt][3],
                            bl4r[nt][0], bl4r[nt][1]);
                mma_bf16(c, al4[mt][0], al4[mt][1], al4[mt][2], al4[mt][3],
                            bh[nt][0], bh[nt][1]);
            }

        if (kb + 1 < NKB) SSTORE(1 - buf);
        __syncthreads();
    }
    #undef GLOAD
    #undef SSTORE

    #pragma unroll
    for (int mt = 0; mt < 4; mt++) {
        #pragma unroll
        for (int nt = 0; nt < 4; nt++) {
            int n  = n0 + wn * 32 + nt * 8 + tg * 2;
            int mA = m0 + wm * 64 + mt * 16 + g;
            float bs0 = __ldg(bias + n), bs1 = __ldg(bias + n + 1);
            float v00 = acc[mt][nt][0] + bs0;
            float v01 = acc[mt][nt][1] + bs1;
            float v10 = acc[mt][nt][2] + bs0;
            float v11 = acc[mt][nt][3] + bs1;
            int t0 = mA >> 1, bb = mA & 1;
            int t1 = (mA + 8) >> 1;
            if (MODE == 0) {
                if (n < HD) {
                    int h = n >> 6, d2 = (n & 63) >> 1;
                    size_t base = ((size_t)(bb * HEADS + h)) * 32 * T_LEN + (size_t)d2 * T_LEN;
                    uint32_t hw, lw;
                    sp2(v00, v01, hw, lw);
                    g_KhT[base + t0] = hw;
                    g_KlT[base + t0] = lw;
                    sp2(v10, v11, hw, lw);
                    g_KhT[base + t1] = hw;
                    g_KlT[base + t1] = lw;
                } else {
                    int nn = n - HD;
                    int h = nn >> 6, d = nn & 63;
                    size_t base = (((size_t)(bb * HEADS + h)) * T_LEN) * HDIM + d;
                    g_V[base + (size_t)t0 * HDIM]     = v00;
                    g_V[base + (size_t)t0 * HDIM + 1] = v01;
                    g_V[base + (size_t)t1 * HDIM]     = v10;
                    g_V[base + (size_t)t1 * HDIM + 1] = v11;
                }
            } else if (MODE == 1) {
                float u0 = __ldg(u + n), u1 = __ldg(u + n + 1);
                int h = n >> 6, d2 = (n & 63) >> 1;
                size_t base = ((size_t)(bb * HEADS + h)) * S_LEN;
                uint32_t hw, lw;
                sp2(v00 + u0, v01 + u1, hw, lw);
                g_Qh[(base + t0) * 32 + d2] = hw;
                g_Ql[(base + t0) * 32 + d2] = lw;
                sp2(v10 + u0, v11 + u1, hw, lw);
                g_Qh[(base + t1) * 32 + d2] = hw;
                g_Ql[(base + t1) * 32 + d2] = lw;
            } else {
                out[(size_t)mA * EDIM + n]           = v00;
                out[(size_t)mA * EDIM + n + 1]       = v01;
                out[(size_t)(mA + 8) * EDIM + n]     = v10;
                out[(size_t)(mA + 8) * EDIM + n + 1] = v11;
            }
        }
    }
}

// ===========================================================================
// Flash attention, 3x-bf16, cp.async double-buffered K/V (pure copies),
// 2 CTAs/SM, mask tile-flags. smem = 110592 B dynamic.
// ===========================================================================
#define PADT 72
#define PADP 36
#define KVBUF (32*PADT)   /* u32 per array */

__global__ __launch_bounds__(256, 2) void attn_bf16(const unsigned char* __restrict__ mask)
{
    extern __shared__ uint32_t smu[];
    uint32_t* Ph = smu + 8 * KVBUF;
    uint32_t* Pl = Ph + 128 * PADP;

    const int bh = blockIdx.y;
    const int b  = bh >> 4;
    const int h  = bh & 15;
    const int s0 = blockIdx.x * 128;
    const int tid = threadIdx.x;
    const int wid = tid >> 5, lane = tid & 31;
    const int g   = lane >> 2, tg = lane & 3;
    const int rowA = wid * 16 + g;

    const uint32_t* KhTg = g_KhT + (size_t)bh * 32 * T_LEN;
    const uint32_t* KlTg = g_KlT + (size_t)bh * 32 * T_LEN;
    const uint32_t* Vh2g = g_Vh2 + (size_t)bh * (T_LEN / 2) * HDIM;
    const uint32_t* Vl2g = g_Vl2 + (size_t)bh * (T_LEN / 2) * HDIM;

    const uint32_t smb = smem_u32(smu);
    const int lr  = tid >> 4;          // 0..15 (use rows lr and lr+16)
    const int lc4 = (tid & 15) * 4;    // col chunk base

    // ---- Q fragments: direct pre-split loads ----
    uint32_t qh[4][4], ql[4][4];
    {
        const uint32_t* qh0 = g_Qh + ((size_t)bh * S_LEN + s0 + rowA) * 32;
        const uint32_t* qh1 = qh0 + 8 * 32;
        const uint32_t* ql0 = g_Ql + ((size_t)bh * S_LEN + s0 + rowA) * 32;
        const uint32_t* ql1 = ql0 + 8 * 32;
        #pragma unroll
        for (int ks = 0; ks < 4; ks++) {
            qh[ks][0] = qh0[ks * 8 + tg];
            qh[ks][1] = qh1[ks * 8 + tg];
            qh[ks][2] = qh0[ks * 8 + tg + 4];
            qh[ks][3] = qh1[ks * 8 + tg + 4];
            ql[ks][0] = ql0[ks * 8 + tg];
            ql[ks][1] = ql1[ks * 8 + tg];
            ql[ks][2] = ql0[ks * 8 + tg + 4];
            ql[ks][3] = ql1[ks * 8 + tg + 4];
        }
    }

    #define LOAD_KV(bf, j0) do { \
        uint32_t kbp = smb + (bf) * (4 * KVBUF * 4); \
        int r0_ = lr, r1_ = lr + 16; \
        uint32_t off0 = (uint32_t)(r0_ * PADT + lc4) * 4; \
        uint32_t off1 = (uint32_t)(r1_ * PADT + lc4) * 4; \
        cpa16(kbp + off0,                 KhTg + (size_t)r0_ * T_LEN + (j0) + lc4); \
        cpa16(kbp + off1,                 KhTg + (size_t)r1_ * T_LEN + (j0) + lc4); \
        cpa16(kbp + KVBUF * 4 + off0,     KlTg + (size_t)r0_ * T_LEN + (j0) + lc4); \
        cpa16(kbp + KVBUF * 4 + off1,     KlTg + (size_t)r1_ * T_LEN + (j0) + lc4); \
        cpa16(kbp + 2 * KVBUF * 4 + off0, Vh2g + (size_t)(((j0) >> 1) + r0_) * HDIM + lc4); \
        cpa16(kbp + 2 * KVBUF * 4 + off1, Vh2g + (size_t)(((j0) >> 1) + r1_) * HDIM + lc4); \
        cpa16(kbp + 3 * KVBUF * 4 + off0, Vl2g + (size_t)(((j0) >> 1) + r0_) * HDIM + lc4); \
        cpa16(kbp + 3 * KVBUF * 4 + off1, Vl2g + (size_t)(((j0) >> 1) + r1_) * HDIM + lc4); \
    } while (0)

    float o[8][4] = {};
    float m0 = -1e30f, m1 = -1e30f, l0 = 0.f, l1 = 0.f;

    LOAD_KV(0, 0);
    CP_COMMIT();

    for (int jt = 0; jt < 32; jt++) {
        const int j0 = jt << 6;
        const int buf = jt & 1;
        if (jt < 31) {
            LOAD_KV(buf ^ 1, j0 + 64);
            CP_COMMIT();
            asm volatile("cp.async.wait_group 1;" ::: "memory");
        } else {
            asm volatile("cp.async.wait_group 0;" ::: "memory");
        }
        int any_mask = g_mflag[blockIdx.x * 32 + jt];
        __syncthreads();

        uint32_t* Kh = smu + buf * 4 * KVBUF;
        uint32_t* Kl = Kh + KVBUF;
        uint32_t* Vh = Kh + 2 * KVBUF;
        uint32_t* Vl = Kh + 3 * KVBUF;

        // ---- S = Q K^T ----
        float sc[8][4] = {};
        #pragma unroll
        for (int ks = 0; ks < 4; ks++) {
            #pragma unroll
            for (int nt = 0; nt < 8; nt++) {
                int n = nt * 8 + g;
                uint32_t b0h = Kh[(ks * 8 + tg)     * PADT + n];
                uint32_t b1h = Kh[(ks * 8 + tg + 4) * PADT + n];
                uint32_t b0l = Kl[(ks * 8 + tg)     * PADT + n];
                uint32_t b1l = Kl[(ks * 8 + tg + 4) * PADT + n];
                mma_bf16(sc[nt], qh[ks][0], qh[ks][1], qh[ks][2], qh[ks][3], b0h, b1h);
                mma_bf16(sc[nt], qh[ks][0], qh[ks][1], qh[ks][2], qh[ks][3], b0l, b1l);
                mma_bf16(sc[nt], ql[ks][0], ql[ks][1], ql[ks][2], ql[ks][3], b0h, b1h);
            }
        }

        #pragma unroll
        for (int nt = 0; nt < 8; nt++) {
            sc[nt][0] *= 0.125f; sc[nt][1] *= 0.125f;
            sc[nt][2] *= 0.125f; sc[nt][3] *= 0.125f;
        }
        if (any_mask) {
            int sg0 = s0 + rowA, sg1 = sg0 + 8;
            #pragma unroll
            for (int nt = 0; nt < 8; nt++) {
                int cg = j0 + nt * 8 + tg * 2;
                const unsigned char* m0p = mask + (size_t)sg0 * T_LEN + cg;
                const unsigned char* m1p = mask + (size_t)sg1 * T_LEN + cg;
                if (m0p[0]) sc[nt][0] = -INFINITY;
                if (m0p[1]) sc[nt][1] = -INFINITY;
                if (m1p[0]) sc[nt][2] = -INFINITY;
                if (m1p[1]) sc[nt][3] = -INFINITY;
            }
        }

        // ---- warp-local online softmax ----
        float mx0 = -1e30f, mx1 = -1e30f;
        #pragma unroll
        for (int nt = 0; nt < 8; nt++) {
            mx0 = fmaxf(mx0, fmaxf(sc[nt][0], sc[nt][1]));
            mx1 = fmaxf(mx1, fmaxf(sc[nt][2], sc[nt][3]));
        }
        mx0 = fmaxf(mx0, __shfl_xor_sync(0xffffffffu, mx0, 1));
        mx0 = fmaxf(mx0, __shfl_xor_sync(0xffffffffu, mx0, 2));
        mx1 = fmaxf(mx1, __shfl_xor_sync(0xffffffffu, mx1, 1));
        mx1 = fmaxf(mx1, __shfl_xor_sync(0xffffffffu, mx1, 2));

        float mn0 = fmaxf(m0, mx0), mn1 = fmaxf(m1, mx1);
        float cr0 = __expf(m0 - mn0), cr1 = __expf(m1 - mn1);
        float ps0 = 0.f, ps1 = 0.f;
        #pragma unroll
        for (int nt = 0; nt < 8; nt++) {
            sc[nt][0] = __expf(sc[nt][0] - mn0);
            sc[nt][1] = __expf(sc[nt][1] - mn0);
            sc[nt][2] = __expf(sc[nt][2] - mn1);
            sc[nt][3] = __expf(sc[nt][3] - mn1);
            ps0 += sc[nt][0] + sc[nt][1];
            ps1 += sc[nt][2] + sc[nt][3];
        }
        ps0 += __shfl_xor_sync(0xffffffffu, ps0, 1);
        ps0 += __shfl_xor_sync(0xffffffffu, ps0, 2);
        ps1 += __shfl_xor_sync(0xffffffffu, ps1, 1);
        ps1 += __shfl_xor_sync(0xffffffffu, ps1, 2);
        l0 = l0 * cr0 + ps0; m0 = mn0;
        l1 = l1 * cr1 + ps1; m1 = mn1;
        #pragma unroll
        for (int nt = 0; nt < 8; nt++) {
            o[nt][0] *= cr0; o[nt][1] *= cr0;
            o[nt][2] *= cr1; o[nt][3] *= cr1;
        }

        // ---- stage P split+packed (warp-private rows) ----
        #pragma unroll
        for (int nt = 0; nt < 8; nt++) {
            int c2 = nt * 4 + tg;
            uint32_t hw, lw;
            sp2(sc[nt][0], sc[nt][1], hw, lw);
            Ph[rowA * PADP + c2] = hw; Pl[rowA * PADP + c2] = lw;
            sp2(sc[nt][2], sc[nt][3], hw, lw);
            Ph[(rowA + 8) * PADP + c2] = hw; Pl[(rowA + 8) * PADP + c2] = lw;
        }
        __syncwarp();

        // ---- O += P V ----
        #pragma unroll
        for (int ks = 0; ks < 4; ks++) {
            uint32_t ah[4], al[4];
            ah[0] = Ph[ rowA      * PADP + ks * 8 + tg];
            ah[1] = Ph[(rowA + 8) * PADP + ks * 8 + tg];
            ah[2] = Ph[ rowA      * PADP + ks * 8 + tg + 4];
            ah[3] = Ph[(rowA + 8) * PADP + ks * 8 + tg + 4];
            al[0] = Pl[ rowA      * PADP + ks * 8 + tg];
            al[1] = Pl[(rowA + 8) * PADP + ks * 8 + tg];
            al[2] = Pl[ rowA      * PADP + ks * 8 + tg + 4];
            al[3] = Pl[(rowA + 8) * PADP + ks * 8 + tg + 4];
            #pragma unroll
            for (int nt = 0; nt < 8; nt++) {
                int n = nt * 8 + g;
                uint32_t b0h = Vh[(ks * 8 + tg)     * PADT + n];
                uint32_t b1h = Vh[(ks * 8 + tg + 4) * PADT + n];
                uint32_t b0l = Vl[(ks * 8 + tg)     * PADT + n];
                uint32_t b1l = Vl[(ks * 8 + tg + 4) * PADT + n];
                mma_bf16(o[nt], ah[0], ah[1], ah[2], ah[3], b0h, b1h);
                mma_bf16(o[nt], ah[0], ah[1], ah[2], ah[3], b0l, b1l);
                mma_bf16(o[nt], al[0], al[1], al[2], al[3], b0h, b1h);
            }
        }
        __syncthreads();   // all warps done with buf before next load overwrites it
    }

    // ---- epilogue: normalize + split-store to g_AVh/g_AVl ----
    float i0 = 1.f / l0, i1 = 1.f / l1;
    int sg0 = s0 + rowA, sg1 = sg0 + 8;
    #pragma unroll
    for (int nt = 0; nt < 8; nt++) {
        int c2 = h * 32 + nt * 4 + tg;
        uint32_t hw, lw;
        sp2(o[nt][0] * i0, o[nt][1] * i0, hw, lw);
        g_AVh[((size_t)sg0 * BATCH + b) * 512 + c2] = hw;
        g_AVl[((size_t)sg0 * BATCH + b) * 512 + c2] = lw;
        sp2(o[nt][2] * i1, o[nt][3] * i1, hw, lw);
        g_AVh[((size_t)sg1 * BATCH + b) * 512 + c2] = hw;
        g_AVl[((size_t)sg1 * BATCH + b) * 512 + c2] = lw;
    }
}

// ---------------------------------------------------------------------------
extern "C" void kernel_launch(void* const* d_in, const int* in_sizes, int n_in,
                              void* d_out, int out_size)
{
    const float* inputs = (const float*)d_in[0];
    const float* enc    = (const float*)d_in[2];
    const float* u      = (const float*)d_in[3];
    const unsigned char* mask = (const unsigned char*)d_in[5];
    const float* Wkv = (const float*)d_in[6];
    const float* bkv = (const float*)d_in[7];
    const float* Wq  = (const float*)d_in[8];
    const float* bq  = (const float*)d_in[9];
    const float* Wp  = (const float*)d_in[10];
    const float* bp  = (const float*)d_in[11];
    float* out = (float*)d_out;

    uint32_t *encH, *encL, *inH, *inL, *wkvH, *wkvL, *wqH, *wqL, *wpH, *wpL, *avH, *avL;
    cudaGetSymbolAddress((void**)&encH, g_encH); cudaGetSymbolAddress((void**)&encL, g_encL);
    cudaGetSymbolAddress((void**)&inH,  g_inH);  cudaGetSymbolAddress((void**)&inL,  g_inL);
    cudaGetSymbolAddress((void**)&wkvH, g_WkvH); cudaGetSymbolAddress((void**)&wkvL, g_WkvL);
    cudaGetSymbolAddress((void**)&wqH,  g_WqH);  cudaGetSymbolAddress((void**)&wqL,  g_WqL);
    cudaGetSymbolAddress((void**)&wpH,  g_WpH);  cudaGetSymbolAddress((void**)&wpL,  g_WpL);
    cudaGetSymbolAddress((void**)&avH,  g_AVh);  cudaGetSymbolAddress((void**)&avL,  g_AVl);

    const int ASMEM = (8 * KVBUF + 2 * 128 * PADP) * 4;   // 110592 B
    cudaFuncSetAttribute(attn_bf16, cudaFuncAttributeMaxDynamicSharedMemorySize, ASMEM);

    dim3 blk(256);
    conv_b<<<1024, blk>>>(Wkv, wkvH, wkvL, 2048);
    conv_b<<<512,  blk>>>(Wq,  wqH,  wqL,  1024);
    conv_b<<<512,  blk>>>(Wp,  wpH,  wpL,  1024);
    conv_a<<<2048, blk>>>(enc,    encH, encL);
    conv_a<<<2048, blk>>>(inputs, inH,  inL);
    mask_scan<<<dim3(16, 32), blk>>>(mask);
    mma_gemm<0><<<dim3(16, 32), blk>>>(encH, encL, wkvH, wkvL, bkv, nullptr, nullptr, 2 * HD);
    conv_v<<<2048, blk>>>();
    mma_gemm<1><<<dim3(8, 32),  blk>>>(inH,  inL,  wqH,  wqL,  bq,  u,       nullptr, HD);
    attn_bf16<<<dim3(S_LEN / 128, BATCH * HEADS), blk, ASMEM>>>(mask);
    mma_gemm<2><<<dim3(8, 32),  blk>>>(avH, avL, wpH, wpL, bp, nullptr, out, HD);
}

// round 12
// speedup vs baseline: 1.1860x; 1.0309x over previous
#include <cuda_runtime.h>
#include <math.h>
#include <stdint.h>

#define S_LEN 2048
#define T_LEN 2048
#define BATCH 2
#define EDIM  1024
#define HEADS 16
#define HDIM  64
#define HD    (HEADS*HDIM)   /* 1024 */

// ---------------- scratch (static device globals; no allocation) ----------
__device__ uint32_t g_encH[4096*512], g_encL[4096*512];   // enc  (T*B, E/2)
__device__ uint32_t g_inH [4096*512], g_inL [4096*512];   // inp  (S*B, E/2)
__device__ uint32_t g_WkvH[512*2048], g_WkvL[512*2048];   // Wkv  (E/2, 2HD)
__device__ uint32_t g_WqH [512*1024], g_WqL [512*1024];   // Wq   (E/2, HD)
__device__ uint32_t g_WpH [512*1024], g_WpL [512*1024];   // Wp   (HD/2, E)
__device__ uint32_t g_KhT[BATCH*HEADS*32*T_LEN], g_KlT[BATCH*HEADS*32*T_LEN]; // (B,H,D/2,T)
__device__ uint32_t g_Qh[BATCH*HEADS*S_LEN*32], g_Ql[BATCH*HEADS*S_LEN*32];   // (B,H,S,D/2)
__device__ float    g_V [BATCH*HEADS*T_LEN*HDIM];                              // (B,H,T,D)
__device__ uint32_t g_Vh2[BATCH*HEADS*(T_LEN/2)*HDIM], g_Vl2[BATCH*HEADS*(T_LEN/2)*HDIM]; // (B,H,T/2,D)
__device__ uint32_t g_AVh[4096*512], g_AVl[4096*512];     // (S*B, HD/2)
__device__ int      g_mflag[16*32];                       // per (s-block, j-tile)

// ---------------- bf16 split helpers ---------------------------------------
__device__ __forceinline__ uint32_t bfbits(float x) {
    uint32_t u = __float_as_uint(x);
    return (u + 0x7FFFu + ((u >> 16) & 1u)) & 0xFFFF0000u;
}
__device__ __forceinline__ void sp2(float e, float o, uint32_t& hw, uint32_t& lw) {
    uint32_t he = bfbits(e), ho = bfbits(o);
    float re = e - __uint_as_float(he);
    float ro = o - __uint_as_float(ho);
    hw = __byte_perm(he, ho, 0x7632);
    lw = __byte_perm(bfbits(re), bfbits(ro), 0x7632);
}
__device__ __forceinline__ void mma_bf16(float* c, uint32_t a0, uint32_t a1,
                                         uint32_t a2, uint32_t a3,
                                         uint32_t b0, uint32_t b1) {
    asm volatile(
        "mma.sync.aligned.m16n8k16.row.col.f32.bf16.bf16.f32 "
        "{%0,%1,%2,%3}, {%4,%5,%6,%7}, {%8,%9}, {%0,%1,%2,%3};"
        : "+f"(c[0]), "+f"(c[1]), "+f"(c[2]), "+f"(c[3])
        : "r"(a0), "r"(a1), "r"(a2), "r"(a3), "r"(b0), "r"(b1));
}
__device__ __forceinline__ uint32_t smem_u32(const void* p) {
    uint32_t a;
    asm("{ .reg .u64 t; cvta.to.shared.u64 t, %1; cvt.u32.u64 %0, t; }"
        : "=r"(a) : "l"(p));
    return a;
}
__device__ __forceinline__ void cpa16(uint32_t dst, const uint32_t* src) {
    asm volatile("cp.async.cg.shared.global [%0], [%1], 16;"
                 :: "r"(dst), "l"(src) : "memory");
}
__device__ __forceinline__ void cpa8(uint32_t dst, const uint32_t* src) {
    asm volatile("cp.async.ca.shared.global [%0], [%1], 8;"
                 :: "r"(dst), "l"(src) : "memory");
}
#define CP_COMMIT() asm volatile("cp.async.commit_group;" ::: "memory")

// ===========================================================================
// conversion kernels (merged)
// ===========================================================================
__device__ __forceinline__ void conv_b_body(const float* W, uint32_t* Wh,
                                            uint32_t* Wl, int N, int idx) {
    int k2 = idx / (N / 4), n4 = (idx % (N / 4)) * 4;
    const float* r0 = W + (size_t)(2 * k2) * N + n4;
    float4 a = *(const float4*)r0;
    float4 b = *(const float4*)(r0 + N);
    uint4 h, l;
    sp2(a.x, b.x, h.x, l.x); sp2(a.y, b.y, h.y, l.y);
    sp2(a.z, b.z, h.z, l.z); sp2(a.w, b.w, h.w, l.w);
    *(uint4*)(Wh + (size_t)k2 * N + n4) = h;
    *(uint4*)(Wl + (size_t)k2 * N + n4) = l;
}
// blocks [0,1024): Wkv, [1024,1536): Wq, [1536,2048): Wp
__global__ __launch_bounds__(256) void conv_w(const float* __restrict__ Wkv,
                                              const float* __restrict__ Wq,
                                              const float* __restrict__ Wp) {
    int bx = blockIdx.x;
    if (bx < 1024)
        conv_b_body(Wkv, g_WkvH, g_WkvL, 2048, bx * 256 + threadIdx.x);
    else if (bx < 1536)
        conv_b_body(Wq, g_WqH, g_WqL, 1024, (bx - 1024) * 256 + threadIdx.x);
    else
        conv_b_body(Wp, g_WpH, g_WpL, 1024, (bx - 1536) * 256 + threadIdx.x);
}
// blocks [0,2048): enc, [2048,4096): inputs
__global__ __launch_bounds__(256) void conv_x(const float* __restrict__ enc,
                                              const float* __restrict__ inp) {
    int bx = blockIdx.x;
    const float* A = (bx < 2048) ? enc : inp;
    uint32_t* Ah = (bx < 2048) ? g_encH : g_inH;
    uint32_t* Al = (bx < 2048) ? g_encL : g_inL;
    int idx = (bx & 2047) * 256 + threadIdx.x;
    int m = idx >> 7, c8 = (idx & 127) * 8;
    float4 f0 = *(const float4*)(A + (size_t)m * 1024 + c8);
    float4 f1 = *(const float4*)(A + (size_t)m * 1024 + c8 + 4);
    uint4 h, l;
    sp2(f0.x, f0.y, h.x, l.x); sp2(f0.z, f0.w, h.y, l.y);
    sp2(f1.x, f1.y, h.z, l.z); sp2(f1.z, f1.w, h.w, l.w);
    *(uint4*)(Ah + (size_t)m * 512 + c8 / 2) = h;
    *(uint4*)(Al + (size_t)m * 512 + c8 / 2) = l;
}
// V fp32 (B,H,T,D) -> pre-split t-paired (B,H,T/2,D) u32
__global__ __launch_bounds__(256) void conv_v() {
    int idx = blockIdx.x * 256 + threadIdx.x;
    int bt2 = idx >> 4;
    int c4  = (idx & 15) * 4;
    const float* src = g_V + (size_t)bt2 * 2 * HDIM + c4;
    float4 a = *(const float4*)src;
    float4 b = *(const float4*)(src + HDIM);
    uint4 h, l;
    sp2(a.x, b.x, h.x, l.x); sp2(a.y, b.y, h.y, l.y);
    sp2(a.z, b.z, h.z, l.z); sp2(a.w, b.w, h.w, l.w);
    *(uint4*)(g_Vh2 + (size_t)bt2 * HDIM + c4) = h;
    *(uint4*)(g_Vl2 + (size_t)bt2 * HDIM + c4) = l;
}
// mask tile-flag pre-scan
__global__ __launch_bounds__(256) void mask_scan(const unsigned char* __restrict__ mask) {
    const unsigned char* base = mask + (size_t)(blockIdx.x * 128) * T_LEN + blockIdx.y * 64;
    uint32_t m = 0;
    #pragma unroll
    for (int it = 0; it < 2; it++) {
        int idx = threadIdx.x + it * 256;
        int r = idx >> 2, c16 = (idx & 3) * 16;
        uint4 v = *(const uint4*)(base + (size_t)r * T_LEN + c16);
        m |= v.x | v.y | v.z | v.w;
    }
    int any = __syncthreads_or((int)m);
    if (threadIdx.x == 0) g_mflag[blockIdx.x * 32 + blockIdx.y] = any;
}

// ===========================================================================
// 3x-bf16 GEMM, cp.async 3-stage pipeline, pre-split operands.
// A smem [m][kpair] pad 12 (conflict-free); B smem [kpair][n] pad 136.
// Stage = Ah(1536) | Al(1536) | Bh(1088) | Bl(1088) = 5248 u32; 3 stages.
// ===========================================================================
#define PADA 12
#define PADB 136
#define A_SZ (128*PADA)          /* 1536 */
#define B_SZ (8*PADB)            /* 1088 */
#define STG  (2*A_SZ + 2*B_SZ)   /* 5248 u32 per stage */

template<int MODE>
__global__ __launch_bounds__(256) void mma_gemm(
    const uint32_t* __restrict__ Ahg, const uint32_t* __restrict__ Alg,
    const uint32_t* __restrict__ Bhg, const uint32_t* __restrict__ Blg,
    const float* __restrict__ bias, const float* __restrict__ u,
    float* __restrict__ out, int N)
{
    extern __shared__ uint32_t sm[];

    const int tid  = threadIdx.x;
    const int wid  = tid >> 5, lane = tid & 31;
    const int g    = lane >> 2, tg = lane & 3;
    const int wm   = wid >> 2,  wn = wid & 3;
    const int m0   = blockIdx.y * 128, n0 = blockIdx.x * 128;

    const int aRow = tid >> 2;          // 0..63
    const int aKp  = (tid & 3) * 2;     // kpair base 0,2,4,6
    const int bKp  = tid >> 5;          // kpair 0..7
    const int bCol = (tid & 31) * 4;    // 0..124

    const uint32_t smb = smem_u32(sm);

    // issue one K-chunk's copies into stage st (k2 = kpair offset in global)
    #define GEMM_LOAD(st, k2) do { \
        uint32_t sb = smb + (st) * (STG * 4); \
        uint32_t aoff0 = (uint32_t)(aRow * PADA + aKp) * 4; \
        uint32_t aoff1 = (uint32_t)((aRow + 64) * PADA + aKp) * 4; \
        cpa8(sb + aoff0,                    Ahg + (size_t)(m0 + aRow)      * 512 + (k2) + aKp); \
        cpa8(sb + aoff1,                    Ahg + (size_t)(m0 + aRow + 64) * 512 + (k2) + aKp); \
        cpa8(sb + A_SZ * 4 + aoff0,         Alg + (size_t)(m0 + aRow)      * 512 + (k2) + aKp); \
        cpa8(sb + A_SZ * 4 + aoff1,         Alg + (size_t)(m0 + aRow + 64) * 512 + (k2) + aKp); \
        uint32_t boff = (uint32_t)(bKp * PADB + bCol) * 4; \
        cpa16(sb + 2 * A_SZ * 4 + boff,            Bhg + (size_t)((k2) + bKp) * N + n0 + bCol); \
        cpa16(sb + (2 * A_SZ + B_SZ) * 4 + boff,   Blg + (size_t)((k2) + bKp) * N + n0 + bCol); \
    } while (0)

    float acc[4][4][4] = {};

    GEMM_LOAD(0, 0); CP_COMMIT();
    GEMM_LOAD(1, 8); CP_COMMIT();

    const int NKB = 64;
    int st = 0;
    for (int kb = 0; kb < NKB; kb++) {
        if (kb < NKB - 1) {
            asm volatile("cp.async.wait_group 1;" ::: "memory");
        } else {
            asm volatile("cp.async.wait_group 0;" ::: "memory");
        }
        __syncthreads();
        if (kb + 2 < NKB) {
            int st2 = (st + 2 >= 3) ? st - 1 : st + 2;
            GEMM_LOAD(st2, (kb + 2) * 8);
            CP_COMMIT();
        }

        uint32_t* Ah = sm + st * STG;
        uint32_t* Al = Ah + A_SZ;
        uint32_t* Bh = Ah + 2 * A_SZ;
        uint32_t* Bl = Ah + 2 * A_SZ + B_SZ;

        uint32_t ah[4][4], al4[4][4];
        #pragma unroll
        for (int mt = 0; mt < 4; mt++) {
            int r = wm * 64 + mt * 16 + g;
            ah[mt][0]  = Ah[r * PADA + tg];
            ah[mt][1]  = Ah[(r + 8) * PADA + tg];
            ah[mt][2]  = Ah[r * PADA + tg + 4];
            ah[mt][3]  = Ah[(r + 8) * PADA + tg + 4];
            al4[mt][0] = Al[r * PADA + tg];
            al4[mt][1] = Al[(r + 8) * PADA + tg];
            al4[mt][2] = Al[r * PADA + tg + 4];
            al4[mt][3] = Al[(r + 8) * PADA + tg + 4];
        }
        uint32_t bh[4][2], bl4r[4][2];
        #pragma unroll
        for (int nt = 0; nt < 4; nt++) {
            int c = wn * 32 + nt * 8 + g;
            bh[nt][0]   = Bh[tg * PADB + c];
            bh[nt][1]   = Bh[(tg + 4) * PADB + c];
            bl4r[nt][0] = Bl[tg * PADB + c];
            bl4r[nt][1] = Bl[(tg + 4) * PADB + c];
        }
        #pragma unroll
        for (int mt = 0; mt < 4; mt++)
            #pragma unroll
            for (int nt = 0; nt < 4; nt++) {
                float* c = acc[mt][nt];
                mma_bf16(c, ah[mt][0], ah[mt][1], ah[mt][2], ah[mt][3],
                            bh[nt][0], bh[nt][1]);
                mma_bf16(c, ah[mt][0], ah[mt][1], ah[mt][2], ah[mt][3],
                            bl4r[nt][0], bl4r[nt][1]);
                mma_bf16(c, al4[mt][0], al4[mt][1], al4[mt][2], al4[mt][3],
                            bh[nt][0], bh[nt][1]);
            }

        st = (st + 1 >= 3) ? 0 : st + 1;
    }
    #undef GEMM_LOAD

    // ---------------- epilogue ------------------------------------------
    #pragma unroll
    for (int mt = 0; mt < 4; mt++) {
        #pragma unroll
        for (int nt = 0; nt < 4; nt++) {
            int n  = n0 + wn * 32 + nt * 8 + tg * 2;
            int mA = m0 + wm * 64 + mt * 16 + g;
            float bs0 = __ldg(bias + n), bs1 = __ldg(bias + n + 1);
            float v00 = acc[mt][nt][0] + bs0;
            float v01 = acc[mt][nt][1] + bs1;
            float v10 = acc[mt][nt][2] + bs0;
            float v11 = acc[mt][nt][3] + bs1;
            int t0 = mA >> 1, bb = mA & 1;
            int t1 = (mA + 8) >> 1;
            if (MODE == 0) {
                if (n < HD) {
                    int h = n >> 6, d2 = (n & 63) >> 1;
                    size_t base = ((size_t)(bb * HEADS + h)) * 32 * T_LEN + (size_t)d2 * T_LEN;
                    uint32_t hw, lw;
                    sp2(v00, v01, hw, lw);
                    g_KhT[base + t0] = hw;
                    g_KlT[base + t0] = lw;
                    sp2(v10, v11, hw, lw);
                    g_KhT[base + t1] = hw;
                    g_KlT[base + t1] = lw;
                } else {
                    int nn = n - HD;
                    int h = nn >> 6, d = nn & 63;
                    size_t base = (((size_t)(bb * HEADS + h)) * T_LEN) * HDIM + d;
                    g_V[base + (size_t)t0 * HDIM]     = v00;
                    g_V[base + (size_t)t0 * HDIM + 1] = v01;
                    g_V[base + (size_t)t1 * HDIM]     = v10;
                    g_V[base + (size_t)t1 * HDIM + 1] = v11;
                }
            } else if (MODE == 1) {
                float u0 = __ldg(u + n), u1 = __ldg(u + n + 1);
                int h = n >> 6, d2 = (n & 63) >> 1;
                size_t base = ((size_t)(bb * HEADS + h)) * S_LEN;
                uint32_t hw, lw;
                sp2(v00 + u0, v01 + u1, hw, lw);
                g_Qh[(base + t0) * 32 + d2] = hw;
                g_Ql[(base + t0) * 32 + d2] = lw;
                sp2(v10 + u0, v11 + u1, hw, lw);
                g_Qh[(base + t1) * 32 + d2] = hw;
                g_Ql[(base + t1) * 32 + d2] = lw;
            } else {
                out[(size_t)mA * EDIM + n]           = v00;
                out[(size_t)mA * EDIM + n + 1]       = v01;
                out[(size_t)(mA + 8) * EDIM + n]     = v10;
                out[(size_t)(mA + 8) * EDIM + n + 1] = v11;
            }
        }
    }
}

// ===========================================================================
// Flash attention, 3x-bf16, cp.async double-buffered K/V (unchanged R11).
// ===========================================================================
#define PADT 72
#define PADP 36
#define KVBUF (32*PADT)

__global__ __launch_bounds__(256, 2) void attn_bf16(const unsigned char* __restrict__ mask)
{
    extern __shared__ uint32_t smu[];
    uint32_t* Ph = smu + 8 * KVBUF;
    uint32_t* Pl = Ph + 128 * PADP;

    const int bh = blockIdx.y;
    const int b  = bh >> 4;
    const int h  = bh & 15;
    const int s0 = blockIdx.x * 128;
    const int tid = threadIdx.x;
    const int wid = tid >> 5, lane = tid & 31;
    const int g   = lane >> 2, tg = lane & 3;
    const int rowA = wid * 16 + g;

    const uint32_t* KhTg = g_KhT + (size_t)bh * 32 * T_LEN;
    const uint32_t* KlTg = g_KlT + (size_t)bh * 32 * T_LEN;
    const uint32_t* Vh2g = g_Vh2 + (size_t)bh * (T_LEN / 2) * HDIM;
    const uint32_t* Vl2g = g_Vl2 + (size_t)bh * (T_LEN / 2) * HDIM;

    const uint32_t smb = smem_u32(smu);
    const int lr  = tid >> 4;
    const int lc4 = (tid & 15) * 4;

    uint32_t qh[4][4], ql[4][4];
    {
        const uint32_t* qh0 = g_Qh + ((size_t)bh * S_LEN + s0 + rowA) * 32;
        const uint32_t* qh1 = qh0 + 8 * 32;
        const uint32_t* ql0 = g_Ql + ((size_t)bh * S_LEN + s0 + rowA) * 32;
        const uint32_t* ql1 = ql0 + 8 * 32;
        #pragma unroll
        for (int ks = 0; ks < 4; ks++) {
            qh[ks][0] = qh0[ks * 8 + tg];
            qh[ks][1] = qh1[ks * 8 + tg];
            qh[ks][2] = qh0[ks * 8 + tg + 4];
            qh[ks][3] = qh1[ks * 8 + tg + 4];
            ql[ks][0] = ql0[ks * 8 + tg];
            ql[ks][1] = ql1[ks * 8 + tg];
            ql[ks][2] = ql0[ks * 8 + tg + 4];
            ql[ks][3] = ql1[ks * 8 + tg + 4];
        }
    }

    #define LOAD_KV(bf, j0) do { \
        uint32_t kbp = smb + (bf) * (4 * KVBUF * 4); \
        int r0_ = lr, r1_ = lr + 16; \
        uint32_t off0 = (uint32_t)(r0_ * PADT + lc4) * 4; \
        uint32_t off1 = (uint32_t)(r1_ * PADT + lc4) * 4; \
        cpa16(kbp + off0,                 KhTg + (size_t)r0_ * T_LEN + (j0) + lc4); \
        cpa16(kbp + off1,                 KhTg + (size_t)r1_ * T_LEN + (j0) + lc4); \
        cpa16(kbp + KVBUF * 4 + off0,     KlTg + (size_t)r0_ * T_LEN + (j0) + lc4); \
        cpa16(kbp + KVBUF * 4 + off1,     KlTg + (size_t)r1_ * T_LEN + (j0) + lc4); \
        cpa16(kbp + 2 * KVBUF * 4 + off0, Vh2g + (size_t)(((j0) >> 1) + r0_) * HDIM + lc4); \
        cpa16(kbp + 2 * KVBUF * 4 + off1, Vh2g + (size_t)(((j0) >> 1) + r1_) * HDIM + lc4); \
        cpa16(kbp + 3 * KVBUF * 4 + off0, Vl2g + (size_t)(((j0) >> 1) + r0_) * HDIM + lc4); \
        cpa16(kbp + 3 * KVBUF * 4 + off1, Vl2g + (size_t)(((j0) >> 1) + r1_) * HDIM + lc4); \
    } while (0)

    float o[8][4] = {};
    float m0 = -1e30f, m1 = -1e30f, l0 = 0.f, l1 = 0.f;

    LOAD_KV(0, 0);
    CP_COMMIT();

    for (int jt = 0; jt < 32; jt++) {
        const int j0 = jt << 6;
        const int buf = jt & 1;
        if (jt < 31) {
            LOAD_KV(buf ^ 1, j0 + 64);
            CP_COMMIT();
            asm volatile("cp.async.wait_group 1;" ::: "memory");
        } else {
            asm volatile("cp.async.wait_group 0;" ::: "memory");
        }
        int any_mask = g_mflag[blockIdx.x * 32 + jt];
        __syncthreads();

        uint32_t* Kh = smu + buf * 4 * KVBUF;
        uint32_t* Kl = Kh + KVBUF;
        uint32_t* Vh = Kh + 2 * KVBUF;
        uint32_t* Vl = Kh + 3 * KVBUF;

        float sc[8][4] = {};
        #pragma unroll
        for (int ks = 0; ks < 4; ks++) {
            #pragma unroll
            for (int nt = 0; nt < 8; nt++) {
                int n = nt * 8 + g;
                uint32_t b0h = Kh[(ks * 8 + tg)     * PADT + n];
                uint32_t b1h = Kh[(ks * 8 + tg + 4) * PADT + n];
                uint32_t b0l = Kl[(ks * 8 + tg)     * PADT + n];
                uint32_t b1l = Kl[(ks * 8 + tg + 4) * PADT + n];
                mma_bf16(sc[nt], qh[ks][0], qh[ks][1], qh[ks][2], qh[ks][3], b0h, b1h);
                mma_bf16(sc[nt], qh[ks][0], qh[ks][1], qh[ks][2], qh[ks][3], b0l, b1l);
                mma_bf16(sc[nt], ql[ks][0], ql[ks][1], ql[ks][2], ql[ks][3], b0h, b1h);
            }
        }

        #pragma unroll
        for (int nt = 0; nt < 8; nt++) {
            sc[nt][0] *= 0.125f; sc[nt][1] *= 0.125f;
            sc[nt][2] *= 0.125f; sc[nt][3] *= 0.125f;
        }
        if (any_mask) {
            int sg0 = s0 + rowA, sg1 = sg0 + 8;
            #pragma unroll
            for (int nt = 0; nt < 8; nt++) {
                int cg = j0 + nt * 8 + tg * 2;
                const unsigned char* m0p = mask + (size_t)sg0 * T_LEN + cg;
                const unsigned char* m1p = mask + (size_t)sg1 * T_LEN + cg;
                if (m0p[0]) sc[nt][0] = -INFINITY;
                if (m0p[1]) sc[nt][1] = -INFINITY;
                if (m1p[0]) sc[nt][2] = -INFINITY;
                if (m1p[1]) sc[nt][3] = -INFINITY;
            }
        }

        float mx0 = -1e30f, mx1 = -1e30f;
        #pragma unroll
        for (int nt = 0; nt < 8; nt++) {
            mx0 = fmaxf(mx0, fmaxf(sc[nt][0], sc[nt][1]));
            mx1 = fmaxf(mx1, fmaxf(sc[nt][2], sc[nt][3]));
        }
        mx0 = fmaxf(mx0, __shfl_xor_sync(0xffffffffu, mx0, 1));
        mx0 = fmaxf(mx0, __shfl_xor_sync(0xffffffffu, mx0, 2));
        mx1 = fmaxf(mx1, __shfl_xor_sync(0xffffffffu, mx1, 1));
        mx1 = fmaxf(mx1, __shfl_xor_sync(0xffffffffu, mx1, 2));

        float mn0 = fmaxf(m0, mx0), mn1 = fmaxf(m1, mx1);
        float cr0 = __expf(m0 - mn0), cr1 = __expf(m1 - mn1);
        float ps0 = 0.f, ps1 = 0.f;
        #pragma unroll
        for (int nt = 0; nt < 8; nt++) {
            sc[nt][0] = __expf(sc[nt][0] - mn0);
            sc[nt][1] = __expf(sc[nt][1] - mn0);
            sc[nt][2] = __expf(sc[nt][2] - mn1);
            sc[nt][3] = __expf(sc[nt][3] - mn1);
            ps0 += sc[nt][0] + sc[nt][1];
            ps1 += sc[nt][2] + sc[nt][3];
        }
        ps0 += __shfl_xor_sync(0xffffffffu, ps0, 1);
        ps0 += __shfl_xor_sync(0xffffffffu, ps0, 2);
        ps1 += __shfl_xor_sync(0xffffffffu, ps1, 1);
        ps1 += __shfl_xor_sync(0xffffffffu, ps1, 2);
        l0 = l0 * cr0 + ps0; m0 = mn0;
        l1 = l1 * cr1 + ps1; m1 = mn1;
        #pragma unroll
        for (int nt = 0; nt < 8; nt++) {
            o[nt][0] *= cr0; o[nt][1] *= cr0;
            o[nt][2] *= cr1; o[nt][3] *= cr1;
        }

        #pragma unroll
        for (int nt = 0; nt < 8; nt++) {
            int c2 = nt * 4 + tg;
            uint32_t hw, lw;
            sp2(sc[nt][0], sc[nt][1], hw, lw);
            Ph[rowA * PADP + c2] = hw; Pl[rowA * PADP + c2] = lw;
            sp2(sc[nt][2], sc[nt][3], hw, lw);
            Ph[(rowA + 8) * PADP + c2] = hw; Pl[(rowA + 8) * PADP + c2] = lw;
        }
        __syncwarp();

        #pragma unroll
        for (int ks = 0; ks < 4; ks++) {
            uint32_t ah[4], al[4];
            ah[0] = Ph[ rowA      * PADP + ks * 8 + tg];
            ah[1] = Ph[(rowA + 8) * PADP + ks * 8 + tg];
            ah[2] = Ph[ rowA      * PADP + ks * 8 + tg + 4];
            ah[3] = Ph[(rowA + 8) * PADP + ks * 8 + tg + 4];
            al[0] = Pl[ rowA      * PADP + ks * 8 + tg];
            al[1] = Pl[(rowA + 8) * PADP + ks * 8 + tg];
            al[2] = Pl[ rowA      * PADP + ks * 8 + tg + 4];
            al[3] = Pl[(rowA + 8) * PADP + ks * 8 + tg + 4];
            #pragma unroll
            for (int nt = 0; nt < 8; nt++) {
                int n = nt * 8 + g;
                uint32_t b0h = Vh[(ks * 8 + tg)     * PADT + n];
                uint32_t b1h = Vh[(ks * 8 + tg + 4) * PADT + n];
                uint32_t b0l = Vl[(ks * 8 + tg)     * PADT + n];
                uint32_t b1l = Vl[(ks * 8 + tg + 4) * PADT + n];
                mma_bf16(o[nt], ah[0], ah[1], ah[2], ah[3], b0h, b1h);
                mma_bf16(o[nt], ah[0], ah[1], ah[2], ah[3], b0l, b1l);
                mma_bf16(o[nt], al[0], al[1], al[2], al[3], b0h, b1h);
            }
        }
        __syncthreads();
    }

    float i0 = 1.f / l0, i1 = 1.f / l1;
    int sg0 = s0 + rowA, sg1 = sg0 + 8;
    #pragma unroll
    for (int nt = 0; nt < 8; nt++) {
        int c2 = h * 32 + nt * 4 + tg;
        uint32_t hw, lw;
        sp2(o[nt][0] * i0, o[nt][1] * i0, hw, lw);
        g_AVh[((size_t)sg0 * BATCH + b) * 512 + c2] = hw;
        g_AVl[((size_t)sg0 * BATCH + b) * 512 + c2] = lw;
        sp2(o[nt][2] * i1, o[nt][3] * i1, hw, lw);
        g_AVh[((size_t)sg1 * BATCH + b) * 512 + c2] = hw;
        g_AVl[((size_t)sg1 * BATCH + b) * 512 + c2] = lw;
    }
}

// ---------------------------------------------------------------------------
extern "C" void kernel_launch(void* const* d_in, const int* in_sizes, int n_in,
                              void* d_out, int out_size)
{
    const float* inputs = (const float*)d_in[0];
    const float* enc    = (const float*)d_in[2];
    const float* u      = (const float*)d_in[3];
    const unsigned char* mask = (const unsigned char*)d_in[5];
    const float* Wkv = (const float*)d_in[6];
    const float* bkv = (const float*)d_in[7];
    const float* Wq  = (const float*)d_in[8];
    const float* bq  = (const float*)d_in[9];
    const float* Wp  = (const float*)d_in[10];
    const float* bp  = (const float*)d_in[11];
    float* out = (float*)d_out;

    uint32_t *encH, *encL, *inH, *inL, *wkvH, *wkvL, *wqH, *wqL, *wpH, *wpL, *avH, *avL;
    cudaGetSymbolAddress((void**)&encH, g_encH); cudaGetSymbolAddress((void**)&encL, g_encL);
    cudaGetSymbolAddress((void**)&inH,  g_inH);  cudaGetSymbolAddress((void**)&inL,  g_inL);
    cudaGetSymbolAddress((void**)&wkvH, g_WkvH); cudaGetSymbolAddress((void**)&wkvL, g_WkvL);
    cudaGetSymbolAddress((void**)&wqH,  g_WqH);  cudaGetSymbolAddress((void**)&wqL,  g_WqL);
    cudaGetSymbolAddress((void**)&wpH,  g_WpH);  cudaGetSymbolAddress((void**)&wpL,  g_WpL);
    cudaGetSymbolAddress((void**)&avH,  g_AVh);  cudaGetSymbolAddress((void**)&avL,  g_AVl);

    const int GSMEM = 3 * STG * 4;                         // 62976 B
    const int ASMEM = (8 * KVBUF + 2 * 128 * PADP) * 4;    // 110592 B
    cudaFuncSetAttribute(mma_gemm<0>, cudaFuncAttributeMaxDynamicSharedMemorySize, GSMEM);
    cudaFuncSetAttribute(mma_gemm<1>, cudaFuncAttributeMaxDynamicSharedMemorySize, GSMEM);
    cudaFuncSetAttribute(mma_gemm<2>, cudaFuncAttributeMaxDynamicSharedMemorySize, GSMEM);
    cudaFuncSetAttribute(attn_bf16,   cudaFuncAttributeMaxDynamicSharedMemorySize, ASMEM);

    dim3 blk(256);
    conv_w<<<2048, blk>>>(Wkv, Wq, Wp);
    conv_x<<<4096, blk>>>(enc, inputs);
    mask_scan<<<dim3(16, 32), blk>>>(mask);
    mma_gemm<0><<<dim3(16, 32), blk, GSMEM>>>(encH, encL, wkvH, wkvL, bkv, nullptr, nullptr, 2 * HD);
    conv_v<<<2048, blk>>>();
    mma_gemm<1><<<dim3(8, 32),  blk, GSMEM>>>(inH,  inL,  wqH,  wqL,  bq,  u,       nullptr, HD);
    attn_bf16<<<dim3(S_LEN / 128, BATCH * HEADS), blk, ASMEM>>>(mask);
    mma_gemm<2><<<dim3(8, 32),  blk, GSMEM>>>(avH, avL, wpH, wpL, bp, nullptr, out, HD);
}